// round 1
// baseline (speedup 1.0000x reference)
#include <cuda_runtime.h>
#include <math.h>

// Problem constants
#define B 32
#define T 2048
#define D 1024
#define U 1024
#define NROWS (B*T)          // 65536
#define NUT 16               // number of 64-wide u tiles
#define TS 8                 // context t-splits

// GEMM tiling
#define BM 64
#define BN 64
#define BK 16

// Scratch (device globals; no allocation allowed)
__device__ float g_pq[B*U];                 // 128 KB: query@W2 + b2 + b1
__device__ float g_partial[NUT * NROWS];    // 4 MB: per-u-tile partial scores
__device__ float g_ctxp[TS * B * D];        // 1 MB: per-t-split context partials

// ---------------------------------------------------------------------------
// Kernel 1: pq[b,u] = sum_d query[b,d]*W2[d,u] + b2[u] + b1[u]
// ---------------------------------------------------------------------------
__global__ void pq_kernel(const float* __restrict__ query,
                          const float* __restrict__ W2,
                          const float* __restrict__ b1,
                          const float* __restrict__ b2) {
    int b = blockIdx.x;
    __shared__ float q[D];
    for (int i = threadIdx.x; i < D; i += blockDim.x) q[i] = query[b*D + i];
    __syncthreads();

    int u = threadIdx.x;  // 256 threads, 4 u's each at stride 256
    float acc0 = 0.f, acc1 = 0.f, acc2 = 0.f, acc3 = 0.f;
    for (int d = 0; d < D; d++) {
        float qd = q[d];
        const float* w = &W2[(size_t)d*U + u];
        acc0 += qd * w[0];
        acc1 += qd * w[256];
        acc2 += qd * w[512];
        acc3 += qd * w[768];
    }
    g_pq[b*U + u      ] = acc0 + b1[u      ] + b2[u      ];
    g_pq[b*U + u + 256] = acc1 + b1[u + 256] + b2[u + 256];
    g_pq[b*U + u + 512] = acc2 + b1[u + 512] + b2[u + 512];
    g_pq[b*U + u + 768] = acc3 + b1[u + 768] + b2[u + 768];
}

// ---------------------------------------------------------------------------
// Kernel 2: fused score GEMM.
// For each 64-row x 64-u tile: proj = values_tile @ W1_tile (full K=1024),
// then tanh(proj + pq) dot V reduced over the 64 u's -> partial[ut][row].
// ---------------------------------------------------------------------------
__global__ __launch_bounds__(256)
void score_gemm_kernel(const float* __restrict__ A,     // values [B*T, D]
                       const float* __restrict__ W1,    // [D, U]
                       const float* __restrict__ Vv,    // [U]
                       float* __restrict__ partial) {   // [NUT][NROWS]
    const int ut   = blockIdx.x;           // 0..15
    const int rt   = blockIdx.y;           // 0..1023
    const int row0 = rt * BM;
    const int u0   = ut * BN;
    const int bidx = row0 / T;             // batch index (BM divides T)

    __shared__ __align__(16) float As[BK][BM + 4];   // stride 68 (16B-aligned rows)
    __shared__ __align__(16) float Bs[BK][BN + 4];

    const int tid = threadIdx.x;     // 256 threads
    const int tx  = tid % 16;        // u microtile index
    const int ty  = tid / 16;        // row microtile index

    // Load index mapping
    const int a_k  = tid % 16;       // k within tile
    const int a_r  = tid / 16;       // row group: rows a_r + 16*j
    const int b_u  = tid % 64;       // u within tile
    const int b_k4 = tid / 64;       // kk = b_k4 + 4*j

    float acc[4][4] = {};

    for (int k0 = 0; k0 < D; k0 += BK) {
        #pragma unroll
        for (int j = 0; j < 4; j++) {
            int r = a_r + 16*j;
            As[a_k][r] = A[(size_t)(row0 + r)*D + (k0 + a_k)];
        }
        #pragma unroll
        for (int j = 0; j < 4; j++) {
            int kk = b_k4 + 4*j;
            Bs[kk][b_u] = W1[(size_t)(k0 + kk)*U + (u0 + b_u)];
        }
        __syncthreads();

        #pragma unroll
        for (int kk = 0; kk < BK; kk++) {
            float4 ra = *(const float4*)&As[kk][ty*4];
            float4 rb = *(const float4*)&Bs[kk][tx*4];
            acc[0][0] += ra.x*rb.x; acc[0][1] += ra.x*rb.y; acc[0][2] += ra.x*rb.z; acc[0][3] += ra.x*rb.w;
            acc[1][0] += ra.y*rb.x; acc[1][1] += ra.y*rb.y; acc[1][2] += ra.y*rb.z; acc[1][3] += ra.y*rb.w;
            acc[2][0] += ra.z*rb.x; acc[2][1] += ra.z*rb.y; acc[2][2] += ra.z*rb.z; acc[2][3] += ra.z*rb.w;
            acc[3][0] += ra.w*rb.x; acc[3][1] += ra.w*rb.y; acc[3][2] += ra.w*rb.z; acc[3][3] += ra.w*rb.w;
        }
        __syncthreads();
    }

    // Epilogue: tanh(proj + pq) * V, reduce over this thread's 4 u's per row
    float pq[4], vv[4];
    #pragma unroll
    for (int j = 0; j < 4; j++) {
        int u = u0 + tx*4 + j;
        pq[j] = g_pq[bidx*U + u];
        vv[j] = Vv[u];
    }
    float rs[4];
    #pragma unroll
    for (int i = 0; i < 4; i++) {
        float s = 0.f;
        #pragma unroll
        for (int j = 0; j < 4; j++) {
            s += tanhf(acc[i][j] + pq[j]) * vv[j];
        }
        rs[i] = s;
    }

    // Reduce across tx (16 threads share each row)
    __shared__ float red[BM][17];
    #pragma unroll
    for (int i = 0; i < 4; i++) red[ty*4 + i][tx] = rs[i];
    __syncthreads();
    if (tid < BM) {
        float s = 0.f;
        #pragma unroll
        for (int x = 0; x < 16; x++) s += red[tid][x];
        partial[(size_t)ut * NROWS + row0 + tid] = s;
    }
}

// ---------------------------------------------------------------------------
// Kernel 3: per-batch reduce partials + bV + mask, softmax over T.
// Writes attention weights to attn (d_out + B*D).
// ---------------------------------------------------------------------------
__global__ void softmax_kernel(const float* __restrict__ partial,
                               const float* __restrict__ mask,
                               const float* __restrict__ bV,
                               float* __restrict__ attn) {
    const int b = blockIdx.x;
    __shared__ float sc[T];
    __shared__ float redbuf[256];
    const float bv = bV[0];

    for (int t = threadIdx.x; t < T; t += 256) {
        float s = 0.f;
        #pragma unroll
        for (int p = 0; p < NUT; p++) s += partial[(size_t)p*NROWS + b*T + t];
        s += bv + mask[b*T + t] * (-1e9f);
        sc[t] = s;
    }
    __syncthreads();

    // max reduce
    float m = -INFINITY;
    for (int t = threadIdx.x; t < T; t += 256) m = fmaxf(m, sc[t]);
    redbuf[threadIdx.x] = m;
    __syncthreads();
    for (int s = 128; s > 0; s >>= 1) {
        if (threadIdx.x < s) redbuf[threadIdx.x] = fmaxf(redbuf[threadIdx.x], redbuf[threadIdx.x + s]);
        __syncthreads();
    }
    m = redbuf[0];
    __syncthreads();

    // exp + sum
    float sum = 0.f;
    for (int t = threadIdx.x; t < T; t += 256) {
        float e = expf(sc[t] - m);
        sc[t] = e;
        sum += e;
    }
    redbuf[threadIdx.x] = sum;
    __syncthreads();
    for (int s = 128; s > 0; s >>= 1) {
        if (threadIdx.x < s) redbuf[threadIdx.x] += redbuf[threadIdx.x + s];
        __syncthreads();
    }
    const float inv = 1.f / redbuf[0];
    __syncthreads();

    for (int t = threadIdx.x; t < T; t += 256) attn[b*T + t] = sc[t] * inv;
}

// ---------------------------------------------------------------------------
// Kernel 4: context partials: for t-split ts, batch b:
// g_ctxp[ts][b][d] = sum_{t in split} attn[b,t] * values[b,t,d]
// ---------------------------------------------------------------------------
__global__ __launch_bounds__(256)
void context_partial_kernel(const float* __restrict__ values,
                            const float* __restrict__ attn) {
    const int ts = blockIdx.x;   // 0..TS-1
    const int b  = blockIdx.y;   // 0..B-1
    const int t0 = ts * (T / TS);        // 256 tokens per split
    const int tid = threadIdx.x;         // 256 threads, 4 d's each (float4)

    __shared__ float w[T / TS];
    w[tid] = attn[b*T + t0 + tid];
    __syncthreads();

    const float4* vp = (const float4*)(values + ((size_t)b*T + t0) * D) + tid;
    float4 acc = make_float4(0.f, 0.f, 0.f, 0.f);
    #pragma unroll 4
    for (int t = 0; t < T / TS; t++) {
        float4 v = vp[(size_t)t * (D/4)];
        float wt = w[t];
        acc.x += wt * v.x;
        acc.y += wt * v.y;
        acc.z += wt * v.z;
        acc.w += wt * v.w;
    }
    ((float4*)(g_ctxp + ((size_t)ts*B + b) * D))[tid] = acc;
}

// ---------------------------------------------------------------------------
// Kernel 5: sum context partials -> ctx (d_out[0 .. B*D))
// ---------------------------------------------------------------------------
__global__ void context_reduce_kernel(float* __restrict__ ctx) {
    int i = blockIdx.x * 256 + threadIdx.x;   // over B*D = 32768
    float s = 0.f;
    #pragma unroll
    for (int p = 0; p < TS; p++) s += g_ctxp[(size_t)p*B*D + i];
    ctx[i] = s;
}

// ---------------------------------------------------------------------------
extern "C" void kernel_launch(void* const* d_in, const int* in_sizes, int n_in,
                              void* d_out, int out_size) {
    const float* values = (const float*)d_in[0];  // [B,T,D]
    const float* query  = (const float*)d_in[1];  // [B,D]
    const float* mask   = (const float*)d_in[2];  // [B,T]
    const float* W1     = (const float*)d_in[3];  // [D,U]
    const float* b1     = (const float*)d_in[4];  // [U]
    const float* W2     = (const float*)d_in[5];  // [D,U]
    const float* b2     = (const float*)d_in[6];  // [U]
    const float* Vv     = (const float*)d_in[7];  // [U,1]
    const float* bV     = (const float*)d_in[8];  // [1]

    float* ctx  = (float*)d_out;            // [B,D]  = 32768 floats
    float* attn = (float*)d_out + B*D;      // [B,T,1] = 65536 floats

    float* g_partial_p;
    cudaGetSymbolAddress((void**)&g_partial_p, g_partial);

    // 1) pq = query@W2 + b2 + b1
    pq_kernel<<<B, 256>>>(query, W2, b1, b2);

    // 2) fused score GEMM: partial[ut][row] = sum_{u in tile} tanh(values@W1 + pq)[u] * V[u]
    dim3 ggrid(NUT, NROWS / BM);   // (16, 1024)
    score_gemm_kernel<<<ggrid, 256>>>(values, W1, Vv, g_partial_p);

    // 3) reduce partials + mask + softmax -> attention weights
    softmax_kernel<<<B, 256>>>(g_partial_p, mask, bV, attn);

    // 4) context = sum_t attn * values (t-split partials, then reduce)
    dim3 cgrid(TS, B);
    context_partial_kernel<<<cgrid, 256>>>(values, attn);
    context_reduce_kernel<<<(B*D)/256, 256>>>(ctx);
}

// round 3
// speedup vs baseline: 4.4020x; 4.4020x over previous
#include <cuda_runtime.h>
#include <cuda_bf16.h>
#include <math.h>
#include <stdint.h>

// Problem constants
#define B 32
#define T 2048
#define D 1024
#define U 1024
#define NROWS (B*T)          // 65536
#define TS 16                // context t-splits

// ---------------------------------------------------------------------------
// Arch feature detection: tcgen05 needs the sm_103a/sm_100a "a" target.
// Under plain compute_103/sm_103 (what this harness's ptxas showed), fall back
// to mma.sync (HMMA). Both kernels are always launched; exactly one has a body.
// ---------------------------------------------------------------------------
#if defined(__CUDA_ARCH_FEAT_SM103_ALL) || defined(__CUDA_ARCH_FEAT_SM100_ALL)
#define HAS_TCGEN05 1
#else
#define HAS_TCGEN05 0
#endif

// tcgen05 GEMM config
#define GM 128               // rows per CTA
#define GN 256               // u-columns per pass (TMEM 256 fp32 cols)
#define NPASS 4
#define KB 64                // k per pipeline stage
#define NKCH (D/KB)          // 16
#define NTHREADS 256

// idesc: dtype=F32(1<<4), atype=BF16(1<<7), btype=BF16(1<<10), N/8<<17, M/16<<24
#define MMA_IDESC ((8u<<24) | (32u<<17) | (1u<<10) | (1u<<7) | (1u<<4))

// tcgen05 dynamic SMEM layout
#define OF_TM   0u
#define OF_MB   16u
#define OF_AHI  1024u            // 2 stages x 16384
#define OF_ALO  33792u
#define OF_BHI  66560u           // 2 stages x 32768
#define OF_BLO  132096u
#define SMEM_BYTES (197632 + 1024)

// fallback (mma.sync) config
#define FB_NP   8                // u passes of 128
#define FB_KC   16               // k chunks of 64
#define FB_STRIDE 72             // smem row stride (bf16 elems), conflict-free
#define FB_TILE (128*FB_STRIDE)  // 9216 bf16 per split tile
#define FB_SMEM (4*FB_TILE*2)    // 73728 bytes
#define WPAD (D+8)               // padded W row stride for fallback layout

// Scratch (device globals; no allocation allowed)
__device__ float g_pq[B*U];
__device__ float g_score[NROWS];
__device__ float g_ctxp[TS*B*D];
__device__ __align__(16) __nv_bfloat16 g_Bhi[U*WPAD];
__device__ __align__(16) __nv_bfloat16 g_Blo[U*WPAD];

// ---------------------------------------------------------------------------
// Common helpers
// ---------------------------------------------------------------------------
__device__ __forceinline__ uint32_t smem_u32(const void* p) {
    uint32_t a;
    asm("{ .reg .u64 t; cvta.to.shared.u64 t, %1; cvt.u32.u64 %0, t; }" : "=r"(a) : "l"(p));
    return a;
}
__device__ __host__ __forceinline__ uint32_t sw128(uint32_t o) { return o ^ ((o >> 3) & 0x70); }

__device__ __forceinline__ unsigned short bfbits(float v) {
    __nv_bfloat16 b = __float2bfloat16(v);
    return *reinterpret_cast<unsigned short*>(&b);
}

extern __shared__ char dynsmem[];

// ---------------------------------------------------------------------------
// tcgen05-only helpers (referenced only under HAS_TCGEN05)
// ---------------------------------------------------------------------------
__device__ __forceinline__ uint32_t elect1() {
    uint32_t p;
    asm volatile("{ .reg .pred p; elect.sync _|p, 0xFFFFFFFF; selp.b32 %0, 1, 0, p; }" : "=r"(p));
    return p;
}
#if HAS_TCGEN05
__device__ __forceinline__ void tm_alloc(uint32_t smem_dst, uint32_t ncols) {
    asm volatile("tcgen05.alloc.cta_group::1.sync.aligned.shared::cta.b32 [%0], %1;"
                 :: "r"(smem_dst), "r"(ncols) : "memory");
}
__device__ __forceinline__ void tm_relinquish() {
    asm volatile("tcgen05.relinquish_alloc_permit.cta_group::1.sync.aligned;");
}
__device__ __forceinline__ void tm_dealloc(uint32_t tmem, uint32_t ncols) {
    asm volatile("tcgen05.dealloc.cta_group::1.sync.aligned.b32 %0, %1;" :: "r"(tmem), "r"(ncols));
}
__device__ __forceinline__ void mma_f16_ss(uint32_t d_tmem, uint64_t a_desc, uint64_t b_desc,
                                           uint32_t idesc, uint32_t en) {
    asm volatile("{\n\t.reg .pred p;\n\t"
                 "setp.ne.u32 p, %5, 0;\n\t"
                 "tcgen05.mma.cta_group::1.kind::f16 [%0], %1, %2, %3, {%4, %4, %4, %4}, p;\n\t}"
                 :: "r"(d_tmem), "l"(a_desc), "l"(b_desc), "r"(idesc), "r"(0u), "r"(en)
                 : "memory");
}
__device__ __forceinline__ void tm_commit(uint32_t mbar) {
    asm volatile("tcgen05.commit.cta_group::1.mbarrier::arrive::one.shared::cluster.b64 [%0];"
                 :: "r"(mbar) : "memory");
}
__device__ __forceinline__ void tc_fence_after() {
    asm volatile("tcgen05.fence::after_thread_sync;" ::: "memory");
}
__device__ __forceinline__ void tc_fence_before() {
    asm volatile("tcgen05.fence::before_thread_sync;" ::: "memory");
}
__device__ __forceinline__ void tc_wait_ld() {
    asm volatile("tcgen05.wait::ld.sync.aligned;" ::: "memory");
}
#define TCLD32(r, a) \
    asm volatile("tcgen05.ld.sync.aligned.32x32b.x32.b32 " \
        "{%0, %1, %2, %3, %4, %5, %6, %7, %8, %9, %10, %11, %12, %13, %14, %15, " \
        " %16, %17, %18, %19, %20, %21, %22, %23, %24, %25, %26, %27, %28, %29, %30, %31}, [%32];" \
        : "=r"((r)[0]),  "=r"((r)[1]),  "=r"((r)[2]),  "=r"((r)[3]), \
          "=r"((r)[4]),  "=r"((r)[5]),  "=r"((r)[6]),  "=r"((r)[7]), \
          "=r"((r)[8]),  "=r"((r)[9]),  "=r"((r)[10]), "=r"((r)[11]), \
          "=r"((r)[12]), "=r"((r)[13]), "=r"((r)[14]), "=r"((r)[15]), \
          "=r"((r)[16]), "=r"((r)[17]), "=r"((r)[18]), "=r"((r)[19]), \
          "=r"((r)[20]), "=r"((r)[21]), "=r"((r)[22]), "=r"((r)[23]), \
          "=r"((r)[24]), "=r"((r)[25]), "=r"((r)[26]), "=r"((r)[27]), \
          "=r"((r)[28]), "=r"((r)[29]), "=r"((r)[30]), "=r"((r)[31]) \
        : "r"(a))
__device__ __forceinline__ uint64_t make_desc(uint32_t addr) {
    const uint64_t base = (uint64_t(2) << 61) | (uint64_t(1) << 46) |
                          (uint64_t(64) << 32) | (uint64_t(1) << 16);   // SW128, LBO=1, SBO=64
    return base | ((uint64_t)(addr >> 4) & 0x3FFF);
}
#endif  // HAS_TCGEN05

__device__ __forceinline__ void mbar_init(uint32_t a, uint32_t cnt) {
    asm volatile("mbarrier.init.shared.b64 [%0], %1;" :: "r"(a), "r"(cnt) : "memory");
}
__device__ __forceinline__ void mbar_inval(uint32_t a) {
    asm volatile("mbarrier.inval.shared.b64 [%0];" :: "r"(a) : "memory");
}
__device__ __forceinline__ void mbar_wait(uint32_t a, uint32_t parity) {
    uint32_t done;
    asm volatile("{\n\t.reg .pred p;\n\t"
                 "mbarrier.try_wait.parity.acquire.cta.shared::cta.b64 p, [%1], %2;\n\t"
                 "selp.b32 %0, 1, 0, p;\n\t}"
                 : "=r"(done) : "r"(a), "r"(parity) : "memory");
    if (!done) {
        asm volatile("{\n\t.reg .pred P1;\n\t"
                     "WL_%=:\n\t"
                     "mbarrier.try_wait.parity.acquire.cta.shared::cta.b64 P1, [%0], %1, 0x989680;\n\t"
                     "@P1 bra.uni WD_%=;\n\t"
                     "bra.uni WL_%=;\n\t"
                     "WD_%=:\n\t}"
                     :: "r"(a), "r"(parity) : "memory");
    }
}

// ---------------------------------------------------------------------------
// Fallback (mma.sync) helpers — legal on plain compute_103
// ---------------------------------------------------------------------------
__device__ __forceinline__ void ldsm_x4(uint32_t& r0, uint32_t& r1, uint32_t& r2, uint32_t& r3,
                                        uint32_t addr) {
    asm volatile("ldmatrix.sync.aligned.m8n8.x4.shared.b16 {%0,%1,%2,%3}, [%4];"
                 : "=r"(r0), "=r"(r1), "=r"(r2), "=r"(r3) : "r"(addr));
}
__device__ __forceinline__ void mma16816(float* d, const uint32_t* a, uint32_t b0, uint32_t b1) {
    asm volatile("mma.sync.aligned.m16n8k16.row.col.f32.bf16.bf16.f32 "
                 "{%0,%1,%2,%3}, {%4,%5,%6,%7}, {%8,%9}, {%0,%1,%2,%3};"
                 : "+f"(d[0]), "+f"(d[1]), "+f"(d[2]), "+f"(d[3])
                 : "r"(a[0]), "r"(a[1]), "r"(a[2]), "r"(a[3]), "r"(b0), "r"(b1));
}

// ---------------------------------------------------------------------------
// Kernel 1: pq[b,u] = query@W2 + b1 + b2
// ---------------------------------------------------------------------------
__global__ void pq_kernel(const float* __restrict__ query, const float* __restrict__ W2,
                          const float* __restrict__ b1, const float* __restrict__ b2) {
    int b = blockIdx.x;
    __shared__ float q[D];
    for (int i = threadIdx.x; i < D; i += blockDim.x) q[i] = query[b*D + i];
    __syncthreads();
    int u = threadIdx.x;
    float a0 = 0.f, a1 = 0.f, a2 = 0.f, a3 = 0.f;
    for (int d = 0; d < D; d++) {
        float qd = q[d];
        const float* w = &W2[(size_t)d*U + u];
        a0 += qd * w[0];   a1 += qd * w[256];
        a2 += qd * w[512]; a3 += qd * w[768];
    }
    g_pq[b*U + u      ] = a0 + b1[u      ] + b2[u      ];
    g_pq[b*U + u + 256] = a1 + b1[u + 256] + b2[u + 256];
    g_pq[b*U + u + 512] = a2 + b1[u + 512] + b2[u + 512];
    g_pq[b*U + u + 768] = a3 + b1[u + 768] + b2[u + 768];
}

// ---------------------------------------------------------------------------
// Kernel 2: W1 -> bf16 hi/lo. Layout depends on live GEMM path:
//   tcgen05: pre-swizzled SW128 tiles [4 ut][16 kc][256u][64k]
//   fallback: padded linear [U][WPAD]
// ---------------------------------------------------------------------------
__global__ void w1_convert_kernel(const float* __restrict__ W1) {
    const int kc = blockIdx.x;        // 0..15
    const int ut = blockIdx.y;        // 0..3
    const int tid = threadIdx.x;      // 0..255
    const int k0 = kc*KB;
#if HAS_TCGEN05
    const int u = tid;
    const size_t tilebytes = (size_t)(ut*NKCH + kc) * 32768;
    char* dhi = (char*)g_Bhi + tilebytes;
    char* dlo = (char*)g_Blo + tilebytes;
    const int u0 = ut*256;
    for (int k4 = 0; k4 < 16; k4++) {
        float f[4];
        #pragma unroll
        for (int j = 0; j < 4; j++) f[j] = W1[(size_t)(k0 + k4*4 + j)*U + u0 + u];
        unsigned short h[4], l[4];
        #pragma unroll
        for (int j = 0; j < 4; j++) {
            h[j] = bfbits(f[j]);
            __nv_bfloat16 hb = *reinterpret_cast<__nv_bfloat16*>(&h[j]);
            l[j] = bfbits(f[j] - __bfloat162float(hb));
        }
        uint2 hp = make_uint2((uint32_t)h[0] | ((uint32_t)h[1] << 16),
                              (uint32_t)h[2] | ((uint32_t)h[3] << 16));
        uint2 lp = make_uint2((uint32_t)l[0] | ((uint32_t)l[1] << 16),
                              (uint32_t)l[2] | ((uint32_t)l[3] << 16));
        uint32_t off = sw128((uint32_t)u*128 + k4*8);
        *(uint2*)(dhi + off) = hp;
        *(uint2*)(dlo + off) = lp;
    }
#else
    const int u = ut*256 + tid;
    for (int k4 = 0; k4 < 16; k4++) {
        float f[4];
        #pragma unroll
        for (int j = 0; j < 4; j++) f[j] = W1[(size_t)(k0 + k4*4 + j)*U + u];
        unsigned short h[4], l[4];
        #pragma unroll
        for (int j = 0; j < 4; j++) {
            h[j] = bfbits(f[j]);
            __nv_bfloat16 hb = *reinterpret_cast<__nv_bfloat16*>(&h[j]);
            l[j] = bfbits(f[j] - __bfloat162float(hb));
        }
        uint2 hp = make_uint2((uint32_t)h[0] | ((uint32_t)h[1] << 16),
                              (uint32_t)h[2] | ((uint32_t)h[3] << 16));
        uint2 lp = make_uint2((uint32_t)l[0] | ((uint32_t)l[1] << 16),
                              (uint32_t)l[2] | ((uint32_t)l[3] << 16));
        *(uint2*)&g_Bhi[(size_t)u*WPAD + k0 + k4*4] = hp;
        *(uint2*)&g_Blo[(size_t)u*WPAD + k0 + k4*4] = lp;
    }
#endif
}

// ---------------------------------------------------------------------------
// Kernel 3a: tcgen05 score GEMM (body only on sm_103a-class targets)
// ---------------------------------------------------------------------------
__global__ void __launch_bounds__(NTHREADS, 1)
score_gemm_tc(const float* __restrict__ values, const float* __restrict__ Vv) {
#if HAS_TCGEN05
    const uint32_t raw = smem_u32(dynsmem);
    const uint32_t sb = (raw + 1023) & ~1023u;
    char* sbp = dynsmem + (sb - raw);

    const int tid = threadIdx.x;
    const int wid = tid >> 5;
    const int lane = tid & 31;
    const int row0 = blockIdx.x * GM;
    const int bidx = row0 / T;

    if (wid == 0) {
        tm_alloc(sb + OF_TM, 256);
        tm_relinquish();
    }
    if (tid == 0) { mbar_init(sb + OF_MB, 1); mbar_init(sb + OF_MB + 8, 1); }
    __syncthreads();
    const uint32_t tmem = *(volatile uint32_t*)(sbp + OF_TM);

    bool pend[2] = {false, false};
    uint32_t par[2] = {0, 0};
    float score = 0.f;

    const int myrow   = ((wid & 3) << 5) + lane;
    const int colbase = (wid >> 2) * 128;

    for (int pass = 0; pass < NPASS; pass++) {
        for (int kc = 0; kc < NKCH; kc++) {
            const int slot = kc & 1;
            if (pend[slot]) { mbar_wait(sb + OF_MB + 8*slot, par[slot]); par[slot] ^= 1; pend[slot] = false; }

            // fill A: LDG fp32, split to bf16 hi/lo, STS swizzled
            {
                char* ahi = sbp + OF_AHI + slot*16384;
                char* alo = sbp + OF_ALO + slot*16384;
                const float4* src = reinterpret_cast<const float4*>(values) + (size_t)row0*256 + kc*16;
                #pragma unroll
                for (int i = 0; i < 8; i++) {
                    int idx = tid + NTHREADS*i;
                    int r = idx >> 4;
                    int s = idx & 15;
                    float4 v = src[(size_t)r*256 + s];
                    float  f[4] = {v.x, v.y, v.z, v.w};
                    unsigned short h[4], l[4];
                    #pragma unroll
                    for (int j = 0; j < 4; j++) {
                        h[j] = bfbits(f[j]);
                        __nv_bfloat16 hb = *reinterpret_cast<__nv_bfloat16*>(&h[j]);
                        l[j] = bfbits(f[j] - __bfloat162float(hb));
                    }
                    uint32_t off = sw128((uint32_t)r*128 + s*8);
                    *(uint2*)(ahi + off) = make_uint2((uint32_t)h[0] | ((uint32_t)h[1] << 16),
                                                      (uint32_t)h[2] | ((uint32_t)h[3] << 16));
                    *(uint2*)(alo + off) = make_uint2((uint32_t)l[0] | ((uint32_t)l[1] << 16),
                                                      (uint32_t)l[2] | ((uint32_t)l[3] << 16));
                }
            }
            // fill B: flat copy of pre-swizzled tiles
            {
                const size_t tq = (size_t)(pass*NKCH + kc) * 2048;
                const uint4* shq = reinterpret_cast<const uint4*>(g_Bhi) + tq;
                const uint4* slq = reinterpret_cast<const uint4*>(g_Blo) + tq;
                uint4* dhq = (uint4*)(sbp + OF_BHI + slot*32768);
                uint4* dlq = (uint4*)(sbp + OF_BLO + slot*32768);
                #pragma unroll
                for (int i = 0; i < 8; i++) {
                    dhq[tid + NTHREADS*i] = shq[tid + NTHREADS*i];
                    dlq[tid + NTHREADS*i] = slq[tid + NTHREADS*i];
                }
            }
            asm volatile("fence.proxy.async.shared::cta;" ::: "memory");
            __syncthreads();

            if (wid == 0) {
                if (elect1()) {
                    uint64_t adh = make_desc(sb + OF_AHI + slot*16384);
                    uint64_t adl = make_desc(sb + OF_ALO + slot*16384);
                    uint64_t bdh = make_desc(sb + OF_BHI + slot*32768);
                    uint64_t bdl = make_desc(sb + OF_BLO + slot*32768);
                    #pragma unroll
                    for (int ks = 0; ks < 4; ks++) {
                        uint32_t first = (kc == 0 && ks == 0) ? 0u : 1u;
                        mma_f16_ss(tmem, adh + ks*2, bdh + ks*2, MMA_IDESC, first);
                        mma_f16_ss(tmem, adh + ks*2, bdl + ks*2, MMA_IDESC, 1u);
                        mma_f16_ss(tmem, adl + ks*2, bdh + ks*2, MMA_IDESC, 1u);
                    }
                    tm_commit(sb + OF_MB + 8*slot);
                }
            }
            pend[slot] = true;
        }

        #pragma unroll
        for (int s2 = 0; s2 < 2; s2++) {
            if (pend[s2]) { mbar_wait(sb + OF_MB + 8*s2, par[s2]); par[s2] ^= 1; pend[s2] = false; }
        }
        tc_fence_after();

        {
            const float* pqrow = &g_pq[bidx*U + pass*GN + colbase];
            const float* vvrow = &Vv[pass*GN + colbase];
            #pragma unroll
            for (int j = 0; j < 4; j++) {
                uint32_t r[32];
                TCLD32(r, tmem + colbase + j*32);
                tc_wait_ld();
                #pragma unroll
                for (int c = 0; c < 32; c++) {
                    float dv = __uint_as_float(r[c]);
                    score += tanhf(dv + pqrow[j*32 + c]) * vvrow[j*32 + c];
                }
            }
        }
        tc_fence_before();
        __syncthreads();
    }

    __shared__ float red2[GM];
    if (wid < 4)  red2[myrow] = score;
    __syncthreads();
    if (wid >= 4) red2[myrow] += score;
    __syncthreads();
    if (tid < GM) g_score[row0 + tid] = red2[tid];

    if (tid == 0) { mbar_inval(sb + OF_MB); mbar_inval(sb + OF_MB + 8); }
    __syncthreads();
    if (wid == 0) tm_dealloc(tmem, 256);
#endif  // HAS_TCGEN05
}

// ---------------------------------------------------------------------------
// Kernel 3b: fallback mma.sync (HMMA) score GEMM (body only on plain sm_103)
// 512 CTAs x 128 rows; 8 passes of 128 u; K chunks of 64 via SMEM.
// ---------------------------------------------------------------------------
__global__ void __launch_bounds__(256)
score_gemm_mma(const float* __restrict__ values, const float* __restrict__ Vv) {
#if !HAS_TCGEN05
    const int tid  = threadIdx.x;
    const int wid  = tid >> 5;
    const int lane = tid & 31;
    const int row0 = blockIdx.x * 128;
    const int bidx = row0 / T;
    const int c = lane & 3;        // quad column
    const int g = lane >> 2;       // quad group (row within 8)

    __nv_bfloat16* As_hi = (__nv_bfloat16*)dynsmem;
    __nv_bfloat16* As_lo = As_hi + FB_TILE;
    __nv_bfloat16* Bs_hi = As_lo + FB_TILE;
    __nv_bfloat16* Bs_lo = Bs_hi + FB_TILE;
    const uint32_t smb   = smem_u32(dynsmem);
    const uint32_t ahi_b = smb;
    const uint32_t alo_b = smb + FB_TILE*2;
    const uint32_t bhi_b = smb + 2*FB_TILE*2;
    const uint32_t blo_b = smb + 3*FB_TILE*2;

    float score0 = 0.f, score1 = 0.f;

    for (int p = 0; p < FB_NP; p++) {
        const int u0 = p * 128;
        float acc[16][4];
        #pragma unroll
        for (int i = 0; i < 16; i++)
            #pragma unroll
            for (int j = 0; j < 4; j++) acc[i][j] = 0.f;

        for (int kc = 0; kc < FB_KC; kc++) {
            const int k0 = kc * 64;
            // A: 128 rows x 64 k fp32 -> split bf16 hi/lo
            #pragma unroll
            for (int i = 0; i < 8; i++) {
                int idx = tid + 256*i;        // 0..2047
                int r = idx >> 4;
                int s = idx & 15;
                float4 v = *(const float4*)&values[(size_t)(row0 + r)*D + k0 + s*4];
                float f[4] = {v.x, v.y, v.z, v.w};
                unsigned short h[4], l[4];
                #pragma unroll
                for (int j = 0; j < 4; j++) {
                    h[j] = bfbits(f[j]);
                    __nv_bfloat16 hb = *reinterpret_cast<__nv_bfloat16*>(&h[j]);
                    l[j] = bfbits(f[j] - __bfloat162float(hb));
                }
                *(uint2*)&As_hi[r*FB_STRIDE + s*4] =
                    make_uint2((uint32_t)h[0] | ((uint32_t)h[1] << 16),
                               (uint32_t)h[2] | ((uint32_t)h[3] << 16));
                *(uint2*)&As_lo[r*FB_STRIDE + s*4] =
                    make_uint2((uint32_t)l[0] | ((uint32_t)l[1] << 16),
                               (uint32_t)l[2] | ((uint32_t)l[3] << 16));
            }
            // B: 128 u x 64 k bf16 hi/lo from padded-linear g_B
            #pragma unroll
            for (int i = 0; i < 4; i++) {
                int idx = tid + 256*i;        // 0..1023
                int n = idx >> 3;
                int m = idx & 7;
                *(uint4*)&Bs_hi[n*FB_STRIDE + m*8] =
                    *(const uint4*)&g_Bhi[(size_t)(u0 + n)*WPAD + k0 + m*8];
                *(uint4*)&Bs_lo[n*FB_STRIDE + m*8] =
                    *(const uint4*)&g_Blo[(size_t)(u0 + n)*WPAD + k0 + m*8];
            }
            __syncthreads();

            #pragma unroll
            for (int ks = 0; ks < 4; ks++) {
                uint32_t ah[4], al[4];
                uint32_t aoff = ((uint32_t)(16*wid + (lane & 15))*FB_STRIDE
                                 + ks*16 + ((lane >> 4) << 3)) * 2;
                ldsm_x4(ah[0], ah[1], ah[2], ah[3], ahi_b + aoff);
                ldsm_x4(al[0], al[1], al[2], al[3], alo_b + aoff);

                #pragma unroll
                for (int nt2 = 0; nt2 < 8; nt2++) {
                    int mtx = lane >> 3, r8 = lane & 7;
                    uint32_t n   = nt2*16 + ((mtx >> 1) << 3) + r8;
                    uint32_t kof = ks*16 + ((mtx & 1) << 3);
                    uint32_t boff = (n*FB_STRIDE + kof) * 2;
                    uint32_t bh0, bh1, bh2, bh3, bl0, bl1, bl2, bl3;
                    ldsm_x4(bh0, bh1, bh2, bh3, bhi_b + boff);
                    ldsm_x4(bl0, bl1, bl2, bl3, blo_b + boff);
                    mma16816(acc[2*nt2],     ah, bh0, bh1);
                    mma16816(acc[2*nt2],     ah, bl0, bl1);
                    mma16816(acc[2*nt2],     al, bh0, bh1);
                    mma16816(acc[2*nt2 + 1], ah, bh2, bh3);
                    mma16816(acc[2*nt2 + 1], ah, bl2, bl3);
                    mma16816(acc[2*nt2 + 1], al, bh2, bh3);
                }
            }
            __syncthreads();
        }

        // epilogue: score += tanh(acc + pq) * V
        #pragma unroll
        for (int nt = 0; nt < 16; nt++) {
            #pragma unroll
            for (int j = 0; j < 2; j++) {
                int u = u0 + nt*8 + 2*c + j;
                float pqv = g_pq[bidx*U + u];
                float vv  = Vv[u];
                score0 += tanhf(acc[nt][j]     + pqv) * vv;
                score1 += tanhf(acc[nt][2 + j] + pqv) * vv;
            }
        }
    }

    // reduce over the 4 lanes of each quad-row
    score0 += __shfl_xor_sync(0xffffffffu, score0, 1);
    score0 += __shfl_xor_sync(0xffffffffu, score0, 2);
    score1 += __shfl_xor_sync(0xffffffffu, score1, 1);
    score1 += __shfl_xor_sync(0xffffffffu, score1, 2);
    if (c == 0) {
        g_score[row0 + wid*16 + g]     = score0;
        g_score[row0 + wid*16 + 8 + g] = score1;
    }
#endif  // !HAS_TCGEN05
}

// ---------------------------------------------------------------------------
// Kernel 4: mask + softmax over T -> attention weights
// ---------------------------------------------------------------------------
__global__ void softmax_kernel(const float* __restrict__ mask,
                               const float* __restrict__ bV,
                               float* __restrict__ attn) {
    const int b = blockIdx.x;
    __shared__ float sc[T];
    __shared__ float redbuf[256];
    const float bv = bV[0];

    for (int t = threadIdx.x; t < T; t += 256)
        sc[t] = g_score[b*T + t] + bv + mask[b*T + t] * (-1e9f);
    __syncthreads();

    float m = -INFINITY;
    for (int t = threadIdx.x; t < T; t += 256) m = fmaxf(m, sc[t]);
    redbuf[threadIdx.x] = m;
    __syncthreads();
    for (int s = 128; s > 0; s >>= 1) {
        if (threadIdx.x < s) redbuf[threadIdx.x] = fmaxf(redbuf[threadIdx.x], redbuf[threadIdx.x + s]);
        __syncthreads();
    }
    m = redbuf[0];
    __syncthreads();

    float sum = 0.f;
    for (int t = threadIdx.x; t < T; t += 256) {
        float e = expf(sc[t] - m);
        sc[t] = e;
        sum += e;
    }
    redbuf[threadIdx.x] = sum;
    __syncthreads();
    for (int s = 128; s > 0; s >>= 1) {
        if (threadIdx.x < s) redbuf[threadIdx.x] += redbuf[threadIdx.x + s];
        __syncthreads();
    }
    const float inv = 1.f / redbuf[0];
    __syncthreads();

    for (int t = threadIdx.x; t < T; t += 256) attn[b*T + t] = sc[t] * inv;
}

// ---------------------------------------------------------------------------
// Kernel 5/6: context = sum_t attn * values
// ---------------------------------------------------------------------------
__global__ void __launch_bounds__(256)
context_partial_kernel(const float* __restrict__ values,
                       const float* __restrict__ attn) {
    const int ts = blockIdx.x;
    const int b  = blockIdx.y;
    const int t0 = ts * (T / TS);
    const int tid = threadIdx.x;

    __shared__ float w[T / TS];
    if (tid < T / TS) w[tid] = attn[b*T + t0 + tid];
    __syncthreads();

    const float4* vp = (const float4*)(values + ((size_t)b*T + t0) * D) + tid;
    float4 acc = make_float4(0.f, 0.f, 0.f, 0.f);
    #pragma unroll 4
    for (int t = 0; t < T / TS; t++) {
        float4 v = vp[(size_t)t * (D/4)];
        float wt = w[t];
        acc.x += wt * v.x; acc.y += wt * v.y;
        acc.z += wt * v.z; acc.w += wt * v.w;
    }
    ((float4*)(g_ctxp + ((size_t)ts*B + b) * D))[tid] = acc;
}

__global__ void context_reduce_kernel(float* __restrict__ ctx) {
    int i = blockIdx.x * 256 + threadIdx.x;
    float s = 0.f;
    #pragma unroll
    for (int p = 0; p < TS; p++) s += g_ctxp[(size_t)p*B*D + i];
    ctx[i] = s;
}

// ---------------------------------------------------------------------------
extern "C" void kernel_launch(void* const* d_in, const int* in_sizes, int n_in,
                              void* d_out, int out_size) {
    const float* values = (const float*)d_in[0];
    const float* query  = (const float*)d_in[1];
    const float* mask   = (const float*)d_in[2];
    const float* W1     = (const float*)d_in[3];
    const float* b1     = (const float*)d_in[4];
    const float* W2     = (const float*)d_in[5];
    const float* b2     = (const float*)d_in[6];
    const float* Vv     = (const float*)d_in[7];
    const float* bV     = (const float*)d_in[8];

    float* ctx  = (float*)d_out;
    float* attn = (float*)d_out + B*D;

    static bool attr_done = false;
    // (setting attributes every call is idempotent and capture-safe)
    cudaFuncSetAttribute(score_gemm_tc,  cudaFuncAttributeMaxDynamicSharedMemorySize, SMEM_BYTES);
    cudaFuncSetAttribute(score_gemm_mma, cudaFuncAttributeMaxDynamicSharedMemorySize, FB_SMEM);
    (void)attr_done;

    pq_kernel<<<B, 256>>>(query, W2, b1, b2);
    w1_convert_kernel<<<dim3(NKCH, 4), 256>>>(W1);

    // Exactly one of these has a body (compile-time arch feature selection).
    score_gemm_tc <<<NROWS/GM, NTHREADS, SMEM_BYTES>>>(values, Vv);
    score_gemm_mma<<<NROWS/128, 256, FB_SMEM>>>(values, Vv);

    softmax_kernel<<<B, 256>>>(mask, bV, attn);
    dim3 cgrid(TS, B);
    context_partial_kernel<<<cgrid, 256>>>(values, attn);
    context_reduce_kernel<<<(B*D)/256, 256>>>(ctx);
}

// round 4
// speedup vs baseline: 5.1317x; 1.1658x over previous
#include <cuda_runtime.h>
#include <cuda_bf16.h>
#include <math.h>
#include <stdint.h>

// Problem constants
#define B 32
#define T 2048
#define D 1024
#define U 1024
#define NROWS (B*T)          // 65536
#define TS 16                // context t-splits

// ---------------------------------------------------------------------------
// Arch feature detection (proven in round 3: executed SASS takes the tcgen05
// path; the plain compute_103 PTX stage assembles only the mma.sync fallback).
// ---------------------------------------------------------------------------
#if defined(__CUDA_ARCH_FEAT_SM103_ALL) || defined(__CUDA_ARCH_FEAT_SM100_ALL)
#define HAS_TCGEN05 1
#else
#define HAS_TCGEN05 0
#endif

// tcgen05 GEMM config: 128 rows/CTA, N=512 per pass (2x MMA N=256), 2 passes,
// k-chunks of 32 (2 k-steps of 16), SW64 swizzle, B via cp.async.bulk.
#define GM 128
#define KCH 32               // k elements per chunk
#define NKC (D/KCH)          // 32 chunks per pass
#define NP2 2                // u passes of 512
#define NTHREADS 256

// idesc: dtype=F32(1<<4), atype=BF16(1<<7), btype=BF16(1<<10), N/8<<17, M/16<<24
#define MMA_IDESC ((8u<<24) | (32u<<17) | (1u<<10) | (1u<<7) | (1u<<4))

// tcgen05 dynamic SMEM layout (offsets from 1024-aligned base)
#define OF_TM   0u
#define OF_FULL 16u              // 2 mbarriers @16,24 (B-copy complete)
#define OF_DONE 32u              // 2 mbarriers @32,40 (MMA commit)
#define OF_AHI  1024u            // +slot*8192   (8 KB per stage)
#define OF_ALO  17408u           // +slot*8192
#define OF_BHI  33792u           // +slot*32768  (32 KB per stage)
#define OF_BLO  99328u           // +slot*32768
#define SMEM_BYTES (164864 + 2048)

// fallback (mma.sync) config — unchanged from round 3
#define FB_NP   8
#define FB_KC   16
#define FB_STRIDE 72
#define FB_TILE (128*FB_STRIDE)
#define FB_SMEM (4*FB_TILE*2)
#define WPAD (D+8)

// Scratch (device globals; no allocation allowed)
__device__ float g_pq[B*U];
__device__ float g_score[NROWS];
__device__ float g_ctxp[TS*B*D];
// tc layout: 64 tiles (pass*32+kc) x 32768 bytes, SW64-swizzled [512u][32k]
// fallback layout: padded linear [U][WPAD]
__device__ __align__(16) __nv_bfloat16 g_Bhi[U*WPAD];
__device__ __align__(16) __nv_bfloat16 g_Blo[U*WPAD];

// ---------------------------------------------------------------------------
// Common helpers
// ---------------------------------------------------------------------------
__device__ __forceinline__ uint32_t smem_u32(const void* p) {
    uint32_t a;
    asm("{ .reg .u64 t; cvta.to.shared.u64 t, %1; cvt.u32.u64 %0, t; }" : "=r"(a) : "l"(p));
    return a;
}
__device__ __host__ __forceinline__ uint32_t sw64(uint32_t o) { return o ^ ((o >> 3) & 0x30); }

__device__ __forceinline__ unsigned short bfbits(float v) {
    __nv_bfloat16 b = __float2bfloat16(v);
    return *reinterpret_cast<unsigned short*>(&b);
}

extern __shared__ char dynsmem[];

__device__ __forceinline__ uint32_t elect1() {
    uint32_t p;
    asm volatile("{ .reg .pred p; elect.sync _|p, 0xFFFFFFFF; selp.b32 %0, 1, 0, p; }" : "=r"(p));
    return p;
}

#if HAS_TCGEN05
__device__ __forceinline__ void tm_alloc(uint32_t smem_dst, uint32_t ncols) {
    asm volatile("tcgen05.alloc.cta_group::1.sync.aligned.shared::cta.b32 [%0], %1;"
                 :: "r"(smem_dst), "r"(ncols) : "memory");
}
__device__ __forceinline__ void tm_relinquish() {
    asm volatile("tcgen05.relinquish_alloc_permit.cta_group::1.sync.aligned;");
}
__device__ __forceinline__ void tm_dealloc(uint32_t tmem, uint32_t ncols) {
    asm volatile("tcgen05.dealloc.cta_group::1.sync.aligned.b32 %0, %1;" :: "r"(tmem), "r"(ncols));
}
__device__ __forceinline__ void mma_f16_ss(uint32_t d_tmem, uint64_t a_desc, uint64_t b_desc,
                                           uint32_t idesc, uint32_t en) {
    asm volatile("{\n\t.reg .pred p;\n\t"
                 "setp.ne.u32 p, %5, 0;\n\t"
                 "tcgen05.mma.cta_group::1.kind::f16 [%0], %1, %2, %3, {%4, %4, %4, %4}, p;\n\t}"
                 :: "r"(d_tmem), "l"(a_desc), "l"(b_desc), "r"(idesc), "r"(0u), "r"(en)
                 : "memory");
}
__device__ __forceinline__ void tm_commit(uint32_t mbar) {
    asm volatile("tcgen05.commit.cta_group::1.mbarrier::arrive::one.shared::cluster.b64 [%0];"
                 :: "r"(mbar) : "memory");
}
__device__ __forceinline__ void tc_fence_after() {
    asm volatile("tcgen05.fence::after_thread_sync;" ::: "memory");
}
__device__ __forceinline__ void tc_fence_before() {
    asm volatile("tcgen05.fence::before_thread_sync;" ::: "memory");
}
__device__ __forceinline__ void tc_wait_ld() {
    asm volatile("tcgen05.wait::ld.sync.aligned;" ::: "memory");
}
#define TCLD32(r, a) \
    asm volatile("tcgen05.ld.sync.aligned.32x32b.x32.b32 " \
        "{%0, %1, %2, %3, %4, %5, %6, %7, %8, %9, %10, %11, %12, %13, %14, %15, " \
        " %16, %17, %18, %19, %20, %21, %22, %23, %24, %25, %26, %27, %28, %29, %30, %31}, [%32];" \
        : "=r"((r)[0]),  "=r"((r)[1]),  "=r"((r)[2]),  "=r"((r)[3]), \
          "=r"((r)[4]),  "=r"((r)[5]),  "=r"((r)[6]),  "=r"((r)[7]), \
          "=r"((r)[8]),  "=r"((r)[9]),  "=r"((r)[10]), "=r"((r)[11]), \
          "=r"((r)[12]), "=r"((r)[13]), "=r"((r)[14]), "=r"((r)[15]), \
          "=r"((r)[16]), "=r"((r)[17]), "=r"((r)[18]), "=r"((r)[19]), \
          "=r"((r)[20]), "=r"((r)[21]), "=r"((r)[22]), "=r"((r)[23]), \
          "=r"((r)[24]), "=r"((r)[25]), "=r"((r)[26]), "=r"((r)[27]), \
          "=r"((r)[28]), "=r"((r)[29]), "=r"((r)[30]), "=r"((r)[31]) \
        : "r"(a))
// SW64 descriptor: layout_type=4, version=1, SBO=32 (512B = 8 rows x 64B), LBO=1 (16B)
__device__ __forceinline__ uint64_t make_desc64(uint32_t addr) {
    const uint64_t base = (uint64_t(4) << 61) | (uint64_t(1) << 46) |
                          (uint64_t(32) << 32) | (uint64_t(1) << 16);
    return base | ((uint64_t)(addr >> 4) & 0x3FFF);
}
__device__ __forceinline__ void bulk_g2s(uint32_t dst, const void* src, uint32_t bytes, uint32_t mbar) {
    asm volatile("cp.async.bulk.shared::cluster.global.mbarrier::complete_tx::bytes [%0], [%1], %2, [%3];"
                 :: "r"(dst), "l"(src), "r"(bytes), "r"(mbar) : "memory");
}
__device__ __forceinline__ void mbar_expect_tx(uint32_t a, uint32_t bytes) {
    asm volatile("mbarrier.arrive.expect_tx.shared.b64 _, [%0], %1;" :: "r"(a), "r"(bytes) : "memory");
}
#endif  // HAS_TCGEN05

__device__ __forceinline__ void mbar_init(uint32_t a, uint32_t cnt) {
    asm volatile("mbarrier.init.shared.b64 [%0], %1;" :: "r"(a), "r"(cnt) : "memory");
}
__device__ __forceinline__ void mbar_inval(uint32_t a) {
    asm volatile("mbarrier.inval.shared.b64 [%0];" :: "r"(a) : "memory");
}
__device__ __forceinline__ void mbar_wait(uint32_t a, uint32_t parity) {
    uint32_t done;
    asm volatile("{\n\t.reg .pred p;\n\t"
                 "mbarrier.try_wait.parity.acquire.cta.shared::cta.b64 p, [%1], %2;\n\t"
                 "selp.b32 %0, 1, 0, p;\n\t}"
                 : "=r"(done) : "r"(a), "r"(parity) : "memory");
    if (!done) {
        asm volatile("{\n\t.reg .pred P1;\n\t"
                     "WL_%=:\n\t"
                     "mbarrier.try_wait.parity.acquire.cta.shared::cta.b64 P1, [%0], %1, 0x989680;\n\t"
                     "@P1 bra.uni WD_%=;\n\t"
                     "bra.uni WL_%=;\n\t"
                     "WD_%=:\n\t}"
                     :: "r"(a), "r"(parity) : "memory");
    }
}

// ---------------------------------------------------------------------------
// Fallback (mma.sync) helpers — legal on plain compute_103
// ---------------------------------------------------------------------------
__device__ __forceinline__ void ldsm_x4(uint32_t& r0, uint32_t& r1, uint32_t& r2, uint32_t& r3,
                                        uint32_t addr) {
    asm volatile("ldmatrix.sync.aligned.m8n8.x4.shared.b16 {%0,%1,%2,%3}, [%4];"
                 : "=r"(r0), "=r"(r1), "=r"(r2), "=r"(r3) : "r"(addr));
}
__device__ __forceinline__ void mma16816(float* d, const uint32_t* a, uint32_t b0, uint32_t b1) {
    asm volatile("mma.sync.aligned.m16n8k16.row.col.f32.bf16.bf16.f32 "
                 "{%0,%1,%2,%3}, {%4,%5,%6,%7}, {%8,%9}, {%0,%1,%2,%3};"
                 : "+f"(d[0]), "+f"(d[1]), "+f"(d[2]), "+f"(d[3])
                 : "r"(a[0]), "r"(a[1]), "r"(a[2]), "r"(a[3]), "r"(b0), "r"(b1));
}

// ---------------------------------------------------------------------------
// Kernel 1: pq[b,u] = query@W2 + b1 + b2
// ---------------------------------------------------------------------------
__global__ void pq_kernel(const float* __restrict__ query, const float* __restrict__ W2,
                          const float* __restrict__ b1, const float* __restrict__ b2) {
    int b = blockIdx.x;
    __shared__ float q[D];
    for (int i = threadIdx.x; i < D; i += blockDim.x) q[i] = query[b*D + i];
    __syncthreads();
    int u = threadIdx.x;
    float a0 = 0.f, a1 = 0.f, a2 = 0.f, a3 = 0.f;
    for (int d = 0; d < D; d++) {
        float qd = q[d];
        const float* w = &W2[(size_t)d*U + u];
        a0 += qd * w[0];   a1 += qd * w[256];
        a2 += qd * w[512]; a3 += qd * w[768];
    }
    g_pq[b*U + u      ] = a0 + b1[u      ] + b2[u      ];
    g_pq[b*U + u + 256] = a1 + b1[u + 256] + b2[u + 256];
    g_pq[b*U + u + 512] = a2 + b1[u + 512] + b2[u + 512];
    g_pq[b*U + u + 768] = a3 + b1[u + 768] + b2[u + 768];
}

// ---------------------------------------------------------------------------
// Kernel 2: W1 -> bf16 hi/lo, layout per live GEMM path.
// Launched as grid (16,4) = 64 blocks under both paths.
// ---------------------------------------------------------------------------
__global__ void w1_convert_kernel(const float* __restrict__ W1) {
    const int tid = threadIdx.x;      // 0..255
#if HAS_TCGEN05
    // 64 tiles: tile = pass*32 + kc; each tile = [512 u][32 k] SW64 = 32 KB
    const int tile = blockIdx.y * gridDim.x + blockIdx.x;   // 0..63
    const int p  = tile >> 5;
    const int kc = tile & 31;
    const int k0 = kc * KCH;
    char* dhi = (char*)g_Bhi + (size_t)tile * 32768;
    char* dlo = (char*)g_Blo + (size_t)tile * 32768;
    for (int uh = 0; uh < 2; uh++) {
        int ul = uh*256 + tid;                 // 0..511
        int ug = p*512 + ul;                   // global u
        for (int kk4 = 0; kk4 < 8; kk4++) {
            float f[4];
            #pragma unroll
            for (int j = 0; j < 4; j++) f[j] = W1[(size_t)(k0 + kk4*4 + j)*U + ug];
            unsigned short h[4], l[4];
            #pragma unroll
            for (int j = 0; j < 4; j++) {
                h[j] = bfbits(f[j]);
                __nv_bfloat16 hb = *reinterpret_cast<__nv_bfloat16*>(&h[j]);
                l[j] = bfbits(f[j] - __bfloat162float(hb));
            }
            uint2 hp = make_uint2((uint32_t)h[0] | ((uint32_t)h[1] << 16),
                                  (uint32_t)h[2] | ((uint32_t)h[3] << 16));
            uint2 lp = make_uint2((uint32_t)l[0] | ((uint32_t)l[1] << 16),
                                  (uint32_t)l[2] | ((uint32_t)l[3] << 16));
            uint32_t off = sw64((uint32_t)ul*64 + kk4*8);
            *(uint2*)(dhi + off) = hp;
            *(uint2*)(dlo + off) = lp;
        }
    }
#else
    const int kc = blockIdx.x;        // 0..15
    const int ut = blockIdx.y;        // 0..3
    const int k0 = kc*64;
    const int u = ut*256 + tid;
    for (int k4 = 0; k4 < 16; k4++) {
        float f[4];
        #pragma unroll
        for (int j = 0; j < 4; j++) f[j] = W1[(size_t)(k0 + k4*4 + j)*U + u];
        unsigned short h[4], l[4];
        #pragma unroll
        for (int j = 0; j < 4; j++) {
            h[j] = bfbits(f[j]);
            __nv_bfloat16 hb = *reinterpret_cast<__nv_bfloat16*>(&h[j]);
            l[j] = bfbits(f[j] - __bfloat162float(hb));
        }
        uint2 hp = make_uint2((uint32_t)h[0] | ((uint32_t)h[1] << 16),
                              (uint32_t)h[2] | ((uint32_t)h[3] << 16));
        uint2 lp = make_uint2((uint32_t)l[0] | ((uint32_t)l[1] << 16),
                              (uint32_t)l[2] | ((uint32_t)l[3] << 16));
        *(uint2*)&g_Bhi[(size_t)u*WPAD + k0 + k4*4] = hp;
        *(uint2*)&g_Blo[(size_t)u*WPAD + k0 + k4*4] = lp;
    }
#endif
}

// ---------------------------------------------------------------------------
// Kernel 3a: tcgen05 score GEMM. 128 rows x 1024 u per CTA.
// N=512 per pass (2x MMA N=256 into TMEM cols 0-255 / 256-511), 2 passes.
// B streamed via cp.async.bulk from pre-swizzled SW64 tiles; A LDG+split+STS.
// ---------------------------------------------------------------------------
__global__ void __launch_bounds__(NTHREADS, 1)
score_gemm_tc(const float* __restrict__ values, const float* __restrict__ Vv) {
#if HAS_TCGEN05
    const uint32_t raw = smem_u32(dynsmem);
    const uint32_t sb = (raw + 1023) & ~1023u;
    char* sbp = dynsmem + (sb - raw);

    const int tid = threadIdx.x;
    const int wid = tid >> 5;
    const int lane = tid & 31;
    const int row0 = blockIdx.x * GM;
    const int bidx = row0 / T;

    if (wid == 0) {
        tm_alloc(sb + OF_TM, 512);
        tm_relinquish();
    }
    if (tid == 0) {
        mbar_init(sb + OF_FULL,     1); mbar_init(sb + OF_FULL + 8, 1);
        mbar_init(sb + OF_DONE,     1); mbar_init(sb + OF_DONE + 8, 1);
    }
    __syncthreads();
    const uint32_t tmem = *(volatile uint32_t*)(sbp + OF_TM);

    bool pend[2] = {false, false};
    uint32_t par_done[2] = {0, 0};
    uint32_t par_full[2] = {0, 0};
    float score = 0.f;

    const int myrow   = ((wid & 3) << 5) + lane;
    const int colbase = (wid >> 2) * 256;

    for (int pass = 0; pass < NP2; pass++) {
        for (int kc = 0; kc < NKC; kc++) {
            const int g = pass*NKC + kc;          // global chunk / B tile index
            const int slot = g & 1;

            // stage-empty: wait for MMA that last used this slot
            if (pend[slot]) {
                mbar_wait(sb + OF_DONE + 8*slot, par_done[slot]);
                par_done[slot] ^= 1;
                pend[slot] = false;
            }

            // async B copy into this slot (overlaps A-fill + prior MMA)
            if (tid == 0) {
                mbar_expect_tx(sb + OF_FULL + 8*slot, 65536);
                bulk_g2s(sb + OF_BHI + slot*32768, (const char*)g_Bhi + (size_t)g*32768,
                         32768, sb + OF_FULL + 8*slot);
                bulk_g2s(sb + OF_BLO + slot*32768, (const char*)g_Blo + (size_t)g*32768,
                         32768, sb + OF_FULL + 8*slot);
            }

            // A-fill: 128 rows x 32 k fp32 -> bf16 hi/lo, SW64 swizzled
            {
                char* ahi = sbp + OF_AHI + slot*8192;
                char* alo = sbp + OF_ALO + slot*8192;
                const float4* src = reinterpret_cast<const float4*>(values)
                                    + (size_t)row0*256 + kc*8;
                #pragma unroll
                for (int i = 0; i < 4; i++) {
                    int idx = tid + NTHREADS*i;   // 0..1023
                    int r = idx >> 3;
                    int pos = idx & 7;
                    float4 v = src[(size_t)r*256 + pos];
                    float f[4] = {v.x, v.y, v.z, v.w};
                    unsigned short h[4], l[4];
                    #pragma unroll
                    for (int j = 0; j < 4; j++) {
                        h[j] = bfbits(f[j]);
                        __nv_bfloat16 hb = *reinterpret_cast<__nv_bfloat16*>(&h[j]);
                        l[j] = bfbits(f[j] - __bfloat162float(hb));
                    }
                    uint32_t off = sw64((uint32_t)r*64 + pos*8);
                    *(uint2*)(ahi + off) = make_uint2((uint32_t)h[0] | ((uint32_t)h[1] << 16),
                                                      (uint32_t)h[2] | ((uint32_t)h[3] << 16));
                    *(uint2*)(alo + off) = make_uint2((uint32_t)l[0] | ((uint32_t)l[1] << 16),
                                                      (uint32_t)l[2] | ((uint32_t)l[3] << 16));
                }
            }
            asm volatile("fence.proxy.async.shared::cta;" ::: "memory");
            __syncthreads();

            // MMA issue: wait B arrival, 12 MMAs (2 ksteps x 2 u-halves x 3 splits)
            if (wid == 0) {
                if (elect1()) {
                    mbar_wait(sb + OF_FULL + 8*slot, par_full[slot]);
                    uint64_t adh = make_desc64(sb + OF_AHI + slot*8192);
                    uint64_t adl = make_desc64(sb + OF_ALO + slot*8192);
                    uint64_t bdh = make_desc64(sb + OF_BHI + slot*32768);
                    uint64_t bdl = make_desc64(sb + OF_BLO + slot*32768);
                    #pragma unroll
                    for (int ks = 0; ks < 2; ks++) {
                        #pragma unroll
                        for (int uh = 0; uh < 2; uh++) {
                            uint32_t dt = tmem + uh*256;
                            uint64_t ao = (uint64_t)(ks*2);
                            uint64_t bo = (uint64_t)(ks*2 + uh*1024);
                            uint32_t first = (kc == 0 && ks == 0) ? 0u : 1u;
                            mma_f16_ss(dt, adh + ao, bdh + bo, MMA_IDESC, first);
                            mma_f16_ss(dt, adh + ao, bdl + bo, MMA_IDESC, 1u);
                            mma_f16_ss(dt, adl + ao, bdh + bo, MMA_IDESC, 1u);
                        }
                    }
                    tm_commit(sb + OF_DONE + 8*slot);
                }
            }
            par_full[slot] ^= 1;
            pend[slot] = true;
        }

        // drain both slots before reading TMEM
        #pragma unroll
        for (int s2 = 0; s2 < 2; s2++) {
            if (pend[s2]) {
                mbar_wait(sb + OF_DONE + 8*s2, par_done[s2]);
                par_done[s2] ^= 1;
                pend[s2] = false;
            }
        }
        tc_fence_after();

        // epilogue: score += sum_u tanh(D + pq) * V over this pass's 512 u
        {
            const float* pqrow = &g_pq[bidx*U + pass*512 + colbase];
            const float* vvrow = &Vv[pass*512 + colbase];
            #pragma unroll
            for (int j = 0; j < 8; j++) {
                uint32_t r[32];
                TCLD32(r, tmem + colbase + j*32);
                tc_wait_ld();
                #pragma unroll
                for (int c = 0; c < 32; c++) {
                    float dv = __uint_as_float(r[c]);
                    score += tanhf(dv + pqrow[j*32 + c]) * vvrow[j*32 + c];
                }
            }
        }
        tc_fence_before();
        __syncthreads();   // D reads done before next pass's first MMA overwrites D
    }

    __shared__ float red2[GM];
    if (wid < 4)  red2[myrow] = score;
    __syncthreads();
    if (wid >= 4) red2[myrow] += score;
    __syncthreads();
    if (tid < GM) g_score[row0 + tid] = red2[tid];

    if (tid == 0) {
        mbar_inval(sb + OF_FULL); mbar_inval(sb + OF_FULL + 8);
        mbar_inval(sb + OF_DONE); mbar_inval(sb + OF_DONE + 8);
    }
    __syncthreads();
    if (wid == 0) tm_dealloc(tmem, 512);
#endif  // HAS_TCGEN05
}

// ---------------------------------------------------------------------------
// Kernel 3b: fallback mma.sync (HMMA) score GEMM (body only on plain sm_103)
// ---------------------------------------------------------------------------
__global__ void __launch_bounds__(256)
score_gemm_mma(const float* __restrict__ values, const float* __restrict__ Vv) {
#if !HAS_TCGEN05
    const int tid  = threadIdx.x;
    const int wid  = tid >> 5;
    const int lane = tid & 31;
    const int row0 = blockIdx.x * 128;
    const int bidx = row0 / T;
    const int c = lane & 3;
    const int g = lane >> 2;

    __nv_bfloat16* As_hi = (__nv_bfloat16*)dynsmem;
    __nv_bfloat16* As_lo = As_hi + FB_TILE;
    __nv_bfloat16* Bs_hi = As_lo + FB_TILE;
    __nv_bfloat16* Bs_lo = Bs_hi + FB_TILE;
    const uint32_t smb   = smem_u32(dynsmem);
    const uint32_t ahi_b = smb;
    const uint32_t alo_b = smb + FB_TILE*2;
    const uint32_t bhi_b = smb + 2*FB_TILE*2;
    const uint32_t blo_b = smb + 3*FB_TILE*2;

    float score0 = 0.f, score1 = 0.f;

    for (int p = 0; p < FB_NP; p++) {
        const int u0 = p * 128;
        float acc[16][4];
        #pragma unroll
        for (int i = 0; i < 16; i++)
            #pragma unroll
            for (int j = 0; j < 4; j++) acc[i][j] = 0.f;

        for (int kc = 0; kc < FB_KC; kc++) {
            const int k0 = kc * 64;
            #pragma unroll
            for (int i = 0; i < 8; i++) {
                int idx = tid + 256*i;
                int r = idx >> 4;
                int s = idx & 15;
                float4 v = *(const float4*)&values[(size_t)(row0 + r)*D + k0 + s*4];
                float f[4] = {v.x, v.y, v.z, v.w};
                unsigned short h[4], l[4];
                #pragma unroll
                for (int j = 0; j < 4; j++) {
                    h[j] = bfbits(f[j]);
                    __nv_bfloat16 hb = *reinterpret_cast<__nv_bfloat16*>(&h[j]);
                    l[j] = bfbits(f[j] - __bfloat162float(hb));
                }
                *(uint2*)&As_hi[r*FB_STRIDE + s*4] =
                    make_uint2((uint32_t)h[0] | ((uint32_t)h[1] << 16),
                               (uint32_t)h[2] | ((uint32_t)h[3] << 16));
                *(uint2*)&As_lo[r*FB_STRIDE + s*4] =
                    make_uint2((uint32_t)l[0] | ((uint32_t)l[1] << 16),
                               (uint32_t)l[2] | ((uint32_t)l[3] << 16));
            }
            #pragma unroll
            for (int i = 0; i < 4; i++) {
                int idx = tid + 256*i;
                int n = idx >> 3;
                int m = idx & 7;
                *(uint4*)&Bs_hi[n*FB_STRIDE + m*8] =
                    *(const uint4*)&g_Bhi[(size_t)(u0 + n)*WPAD + k0 + m*8];
                *(uint4*)&Bs_lo[n*FB_STRIDE + m*8] =
                    *(const uint4*)&g_Blo[(size_t)(u0 + n)*WPAD + k0 + m*8];
            }
            __syncthreads();

            #pragma unroll
            for (int ks = 0; ks < 4; ks++) {
                uint32_t ah[4], al[4];
                uint32_t aoff = ((uint32_t)(16*wid + (lane & 15))*FB_STRIDE
                                 + ks*16 + ((lane >> 4) << 3)) * 2;
                ldsm_x4(ah[0], ah[1], ah[2], ah[3], ahi_b + aoff);
                ldsm_x4(al[0], al[1], al[2], al[3], alo_b + aoff);

                #pragma unroll
                for (int nt2 = 0; nt2 < 8; nt2++) {
                    int mtx = lane >> 3, r8 = lane & 7;
                    uint32_t n   = nt2*16 + ((mtx >> 1) << 3) + r8;
                    uint32_t kof = ks*16 + ((mtx & 1) << 3);
                    uint32_t boff = (n*FB_STRIDE + kof) * 2;
                    uint32_t bh0, bh1, bh2, bh3, bl0, bl1, bl2, bl3;
                    ldsm_x4(bh0, bh1, bh2, bh3, bhi_b + boff);
                    ldsm_x4(bl0, bl1, bl2, bl3, blo_b + boff);
                    mma16816(acc[2*nt2],     ah, bh0, bh1);
                    mma16816(acc[2*nt2],     ah, bl0, bl1);
                    mma16816(acc[2*nt2],     al, bh0, bh1);
                    mma16816(acc[2*nt2 + 1], ah, bh2, bh3);
                    mma16816(acc[2*nt2 + 1], ah, bl2, bl3);
                    mma16816(acc[2*nt2 + 1], al, bh2, bh3);
                }
            }
            __syncthreads();
        }

        #pragma unroll
        for (int nt = 0; nt < 16; nt++) {
            #pragma unroll
            for (int j = 0; j < 2; j++) {
                int u = u0 + nt*8 + 2*c + j;
                float pqv = g_pq[bidx*U + u];
                float vv  = Vv[u];
                score0 += tanhf(acc[nt][j]     + pqv) * vv;
                score1 += tanhf(acc[nt][2 + j] + pqv) * vv;
            }
        }
    }

    score0 += __shfl_xor_sync(0xffffffffu, score0, 1);
    score0 += __shfl_xor_sync(0xffffffffu, score0, 2);
    score1 += __shfl_xor_sync(0xffffffffu, score1, 1);
    score1 += __shfl_xor_sync(0xffffffffu, score1, 2);
    if (c == 0) {
        g_score[row0 + wid*16 + g]     = score0;
        g_score[row0 + wid*16 + 8 + g] = score1;
    }
#endif  // !HAS_TCGEN05
}

// ---------------------------------------------------------------------------
// Kernel 4: mask + softmax over T -> attention weights
// ---------------------------------------------------------------------------
__global__ void softmax_kernel(const float* __restrict__ mask,
                               const float* __restrict__ bV,
                               float* __restrict__ attn) {
    const int b = blockIdx.x;
    __shared__ float sc[T];
    __shared__ float redbuf[256];
    const float bv = bV[0];

    for (int t = threadIdx.x; t < T; t += 256)
        sc[t] = g_score[b*T + t] + bv + mask[b*T + t] * (-1e9f);
    __syncthreads();

    float m = -INFINITY;
    for (int t = threadIdx.x; t < T; t += 256) m = fmaxf(m, sc[t]);
    redbuf[threadIdx.x] = m;
    __syncthreads();
    for (int s = 128; s > 0; s >>= 1) {
        if (threadIdx.x < s) redbuf[threadIdx.x] = fmaxf(redbuf[threadIdx.x], redbuf[threadIdx.x + s]);
        __syncthreads();
    }
    m = redbuf[0];
    __syncthreads();

    float sum = 0.f;
    for (int t = threadIdx.x; t < T; t += 256) {
        float e = expf(sc[t] - m);
        sc[t] = e;
        sum += e;
    }
    redbuf[threadIdx.x] = sum;
    __syncthreads();
    for (int s = 128; s > 0; s >>= 1) {
        if (threadIdx.x < s) redbuf[threadIdx.x] += redbuf[threadIdx.x + s];
        __syncthreads();
    }
    const float inv = 1.f / redbuf[0];
    __syncthreads();

    for (int t = threadIdx.x; t < T; t += 256) attn[b*T + t] = sc[t] * inv;
}

// ---------------------------------------------------------------------------
// Kernel 5/6: context = sum_t attn * values
// ---------------------------------------------------------------------------
__global__ void __launch_bounds__(256)
context_partial_kernel(const float* __restrict__ values,
                       const float* __restrict__ attn) {
    const int ts = blockIdx.x;
    const int b  = blockIdx.y;
    const int t0 = ts * (T / TS);
    const int tid = threadIdx.x;

    __shared__ float w[T / TS];
    if (tid < T / TS) w[tid] = attn[b*T + t0 + tid];
    __syncthreads();

    const float4* vp = (const float4*)(values + ((size_t)b*T + t0) * D) + tid;
    float4 acc = make_float4(0.f, 0.f, 0.f, 0.f);
    #pragma unroll 4
    for (int t = 0; t < T / TS; t++) {
        float4 v = vp[(size_t)t * (D/4)];
        float wt = w[t];
        acc.x += wt * v.x; acc.y += wt * v.y;
        acc.z += wt * v.z; acc.w += wt * v.w;
    }
    ((float4*)(g_ctxp + ((size_t)ts*B + b) * D))[tid] = acc;
}

__global__ void context_reduce_kernel(float* __restrict__ ctx) {
    int i = blockIdx.x * 256 + threadIdx.x;
    float s = 0.f;
    #pragma unroll
    for (int p = 0; p < TS; p++) s += g_ctxp[(size_t)p*B*D + i];
    ctx[i] = s;
}

// ---------------------------------------------------------------------------
extern "C" void kernel_launch(void* const* d_in, const int* in_sizes, int n_in,
                              void* d_out, int out_size) {
    const float* values = (const float*)d_in[0];
    const float* query  = (const float*)d_in[1];
    const float* mask   = (const float*)d_in[2];
    const float* W1     = (const float*)d_in[3];
    const float* b1     = (const float*)d_in[4];
    const float* W2     = (const float*)d_in[5];
    const float* b2     = (const float*)d_in[6];
    const float* Vv     = (const float*)d_in[7];
    const float* bV     = (const float*)d_in[8];

    float* ctx  = (float*)d_out;
    float* attn = (float*)d_out + B*D;

    cudaFuncSetAttribute(score_gemm_tc,  cudaFuncAttributeMaxDynamicSharedMemorySize, SMEM_BYTES);
    cudaFuncSetAttribute(score_gemm_mma, cudaFuncAttributeMaxDynamicSharedMemorySize, FB_SMEM);

    pq_kernel<<<B, 256>>>(query, W2, b1, b2);
    w1_convert_kernel<<<dim3(16, 4), 256>>>(W1);

    // Exactly one of these has a body (compile-time arch feature selection).
    score_gemm_tc <<<NROWS/GM, NTHREADS, SMEM_BYTES>>>(values, Vv);
    score_gemm_mma<<<NROWS/128, 256, FB_SMEM>>>(values, Vv);

    softmax_kernel<<<B, 256>>>(mask, bV, attn);
    dim3 cgrid(TS, B);
    context_partial_kernel<<<cgrid, 256>>>(values, attn);
    context_reduce_kernel<<<(B*D)/256, 256>>>(ctx);
}

// round 6
// speedup vs baseline: 5.8876x; 1.1473x over previous
#include <cuda_runtime.h>
#include <cuda_bf16.h>
#include <math.h>
#include <stdint.h>

// Problem constants
#define B 32
#define T 2048
#define D 1024
#define U 1024
#define NROWS (B*T)          // 65536
#define TS 16                // context t-splits

#if defined(__CUDA_ARCH_FEAT_SM103_ALL) || defined(__CUDA_ARCH_FEAT_SM100_ALL)
#define HAS_TCGEN05 1
#else
#define HAS_TCGEN05 0
#endif

// tcgen05 GEMM config: 256 rows/CTA (2 row-tiles), N=256 per pass, 4 passes,
// k-chunks of 32 (2 k-steps), SW64, pre-split A+B streamed via cp.async.bulk.
#define GM 256
#define KCH 32
#define NKC 32               // chunks per pass (D/KCH)
#define NPASS 4
#define NCH 128              // total chunks = NPASS*NKC
#define NTHREADS 256

// idesc: dtype=F32(1<<4), atype=BF16(1<<7), btype=BF16(1<<10), N/8<<17, M/16<<24
#define MMA_IDESC ((8u<<24) | (32u<<17) | (1u<<10) | (1u<<7) | (1u<<4))

// SMEM layout (offsets from 1024-aligned base)
#define OF_TM   0u
#define OF_FULL 16u              // 3 mbarriers @16,24,32
#define OF_DONE 40u              // 3 mbarriers @40,48,56
#define OF_STG  1024u            // 3 stages x 65536
#define SOF_AHI 0u
#define SOF_ALO 16384u
#define SOF_BHI 32768u
#define SOF_BLO 49152u
#define STG_BYTES 65536u
#define SMEM_BYTES (1024 + 3*65536 + 1024)

// fallback (mma.sync) config — unchanged
#define FB_NP   8
#define FB_KC   16
#define FB_STRIDE 72
#define FB_TILE (128*FB_STRIDE)
#define FB_SMEM (4*FB_TILE*2)
#define WPAD (D+8)

// Scratch (device globals; no allocation allowed)
__device__ float g_pq[B*U];
__device__ float g_score[NROWS];
__device__ float g_ctxp[TS*B*D];
// tc: A granules [256 rowblocks][32 kc][16KB SW64 (256r x 32k)]
__device__ __align__(16) __nv_bfloat16 g_Ahi[NROWS*D];   // 128 MB
__device__ __align__(16) __nv_bfloat16 g_Alo[NROWS*D];   // 128 MB
// tc: B granules [4 pass][32 kc][16KB SW64 (256u x 32k)]; fallback: [U][WPAD]
__device__ __align__(16) __nv_bfloat16 g_Bhi[U*WPAD];
__device__ __align__(16) __nv_bfloat16 g_Blo[U*WPAD];

// ---------------------------------------------------------------------------
// Common helpers
// ---------------------------------------------------------------------------
__device__ __forceinline__ uint32_t smem_u32(const void* p) {
    uint32_t a;
    asm("{ .reg .u64 t; cvta.to.shared.u64 t, %1; cvt.u32.u64 %0, t; }" : "=r"(a) : "l"(p));
    return a;
}
__device__ __host__ __forceinline__ uint32_t sw64(uint32_t o) { return o ^ ((o >> 3) & 0x30); }

__device__ __forceinline__ unsigned short bfbits(float v) {
    __nv_bfloat16 b = __float2bfloat16(v);
    return *reinterpret_cast<unsigned short*>(&b);
}
__device__ __forceinline__ float fast_tanh(float x) {
    float ax = fabsf(x);
    float e = __expf(ax + ax);
    float t = 1.0f - __fdividef(2.0f, e + 1.0f);
    return copysignf(t, x);
}

extern __shared__ char dynsmem[];

#if HAS_TCGEN05
__device__ __forceinline__ void tm_alloc(uint32_t smem_dst, uint32_t ncols) {
    asm volatile("tcgen05.alloc.cta_group::1.sync.aligned.shared::cta.b32 [%0], %1;"
                 :: "r"(smem_dst), "r"(ncols) : "memory");
}
__device__ __forceinline__ void tm_relinquish() {
    asm volatile("tcgen05.relinquish_alloc_permit.cta_group::1.sync.aligned;");
}
__device__ __forceinline__ void tm_dealloc(uint32_t tmem, uint32_t ncols) {
    asm volatile("tcgen05.dealloc.cta_group::1.sync.aligned.b32 %0, %1;" :: "r"(tmem), "r"(ncols));
}
__device__ __forceinline__ void mma_f16_ss(uint32_t d_tmem, uint64_t a_desc, uint64_t b_desc,
                                           uint32_t idesc, uint32_t en) {
    asm volatile("{\n\t.reg .pred p;\n\t"
                 "setp.ne.u32 p, %5, 0;\n\t"
                 "tcgen05.mma.cta_group::1.kind::f16 [%0], %1, %2, %3, {%4, %4, %4, %4}, p;\n\t}"
                 :: "r"(d_tmem), "l"(a_desc), "l"(b_desc), "r"(idesc), "r"(0u), "r"(en)
                 : "memory");
}
__device__ __forceinline__ void tm_commit(uint32_t mbar) {
    asm volatile("tcgen05.commit.cta_group::1.mbarrier::arrive::one.shared::cluster.b64 [%0];"
                 :: "r"(mbar) : "memory");
}
__device__ __forceinline__ void tc_fence_after() {
    asm volatile("tcgen05.fence::after_thread_sync;" ::: "memory");
}
__device__ __forceinline__ void tc_fence_before() {
    asm volatile("tcgen05.fence::before_thread_sync;" ::: "memory");
}
__device__ __forceinline__ void tc_wait_ld() {
    asm volatile("tcgen05.wait::ld.sync.aligned;" ::: "memory");
}
#define TCLD32(r, a) \
    asm volatile("tcgen05.ld.sync.aligned.32x32b.x32.b32 " \
        "{%0, %1, %2, %3, %4, %5, %6, %7, %8, %9, %10, %11, %12, %13, %14, %15, " \
        " %16, %17, %18, %19, %20, %21, %22, %23, %24, %25, %26, %27, %28, %29, %30, %31}, [%32];" \
        : "=r"((r)[0]),  "=r"((r)[1]),  "=r"((r)[2]),  "=r"((r)[3]), \
          "=r"((r)[4]),  "=r"((r)[5]),  "=r"((r)[6]),  "=r"((r)[7]), \
          "=r"((r)[8]),  "=r"((r)[9]),  "=r"((r)[10]), "=r"((r)[11]), \
          "=r"((r)[12]), "=r"((r)[13]), "=r"((r)[14]), "=r"((r)[15]), \
          "=r"((r)[16]), "=r"((r)[17]), "=r"((r)[18]), "=r"((r)[19]), \
          "=r"((r)[20]), "=r"((r)[21]), "=r"((r)[22]), "=r"((r)[23]), \
          "=r"((r)[24]), "=r"((r)[25]), "=r"((r)[26]), "=r"((r)[27]), \
          "=r"((r)[28]), "=r"((r)[29]), "=r"((r)[30]), "=r"((r)[31]) \
        : "r"(a))
// SW64 descriptor: layout_type=4, version=1, SBO=32 (512B = 8 rows x 64B), LBO=1
__device__ __forceinline__ uint64_t make_desc64(uint32_t addr) {
    const uint64_t base = (uint64_t(4) << 61) | (uint64_t(1) << 46) |
                          (uint64_t(32) << 32) | (uint64_t(1) << 16);
    return base | ((uint64_t)(addr >> 4) & 0x3FFF);
}
__device__ __forceinline__ void bulk_g2s(uint32_t dst, const void* src, uint32_t bytes, uint32_t mbar) {
    asm volatile("cp.async.bulk.shared::cluster.global.mbarrier::complete_tx::bytes [%0], [%1], %2, [%3];"
                 :: "r"(dst), "l"(src), "r"(bytes), "r"(mbar) : "memory");
}
__device__ __forceinline__ void mbar_expect_tx(uint32_t a, uint32_t bytes) {
    asm volatile("mbarrier.arrive.expect_tx.shared.b64 _, [%0], %1;" :: "r"(a), "r"(bytes) : "memory");
}
#endif  // HAS_TCGEN05

__device__ __forceinline__ void mbar_init(uint32_t a, uint32_t cnt) {
    asm volatile("mbarrier.init.shared.b64 [%0], %1;" :: "r"(a), "r"(cnt) : "memory");
}
__device__ __forceinline__ void mbar_inval(uint32_t a) {
    asm volatile("mbarrier.inval.shared.b64 [%0];" :: "r"(a) : "memory");
}
__device__ __forceinline__ void mbar_wait(uint32_t a, uint32_t parity) {
    uint32_t done;
    asm volatile("{\n\t.reg .pred p;\n\t"
                 "mbarrier.try_wait.parity.acquire.cta.shared::cta.b64 p, [%1], %2;\n\t"
                 "selp.b32 %0, 1, 0, p;\n\t}"
                 : "=r"(done) : "r"(a), "r"(parity) : "memory");
    if (!done) {
        asm volatile("{\n\t.reg .pred P1;\n\t"
                     "WL_%=:\n\t"
                     "mbarrier.try_wait.parity.acquire.cta.shared::cta.b64 P1, [%0], %1, 0x989680;\n\t"
                     "@P1 bra.uni WD_%=;\n\t"
                     "bra.uni WL_%=;\n\t"
                     "WD_%=:\n\t}"
                     :: "r"(a), "r"(parity) : "memory");
    }
}

// ---------------------------------------------------------------------------
// Fallback (mma.sync) helpers — legal on plain compute_103
// ---------------------------------------------------------------------------
__device__ __forceinline__ void ldsm_x4(uint32_t& r0, uint32_t& r1, uint32_t& r2, uint32_t& r3,
                                        uint32_t addr) {
    asm volatile("ldmatrix.sync.aligned.m8n8.x4.shared.b16 {%0,%1,%2,%3}, [%4];"
                 : "=r"(r0), "=r"(r1), "=r"(r2), "=r"(r3) : "r"(addr));
}
__device__ __forceinline__ void mma16816(float* d, const uint32_t* a, uint32_t b0, uint32_t b1) {
    asm volatile("mma.sync.aligned.m16n8k16.row.col.f32.bf16.bf16.f32 "
                 "{%0,%1,%2,%3}, {%4,%5,%6,%7}, {%8,%9}, {%0,%1,%2,%3};"
                 : "+f"(d[0]), "+f"(d[1]), "+f"(d[2]), "+f"(d[3])
                 : "r"(a[0]), "r"(a[1]), "r"(a[2]), "r"(a[3]), "r"(b0), "r"(b1));
}

// ---------------------------------------------------------------------------
// Kernel 1: pq[b,u] = query@W2 + b1 + b2
// ---------------------------------------------------------------------------
__global__ void pq_kernel(const float* __restrict__ query, const float* __restrict__ W2,
                          const float* __restrict__ b1, const float* __restrict__ b2) {
    int b = blockIdx.x;
    __shared__ float q[D];
    for (int i = threadIdx.x; i < D; i += blockDim.x) q[i] = query[b*D + i];
    __syncthreads();
    int u = threadIdx.x;
    float a0 = 0.f, a1 = 0.f, a2 = 0.f, a3 = 0.f;
    for (int d = 0; d < D; d++) {
        float qd = q[d];
        const float* w = &W2[(size_t)d*U + u];
        a0 += qd * w[0];   a1 += qd * w[256];
        a2 += qd * w[512]; a3 += qd * w[768];
    }
    g_pq[b*U + u      ] = a0 + b1[u      ] + b2[u      ];
    g_pq[b*U + u + 256] = a1 + b1[u + 256] + b2[u + 256];
    g_pq[b*U + u + 512] = a2 + b1[u + 512] + b2[u + 512];
    g_pq[b*U + u + 768] = a3 + b1[u + 768] + b2[u + 768];
}

// ---------------------------------------------------------------------------
// Kernel 2: W1 -> bf16 hi/lo tiles. Grid (32, 4).
//   tc: granule g = pass*32+kc : [256 u][32 k] SW64, 16 KB
//   fallback: padded linear [U][WPAD]
// ---------------------------------------------------------------------------
__global__ void w1_convert_kernel(const float* __restrict__ W1) {
    const int tid = threadIdx.x;      // 0..255
#if HAS_TCGEN05
    const int kc   = blockIdx.x;      // 0..31
    const int pass = blockIdx.y;      // 0..3
    const int g = pass*32 + kc;
    char* dhi = (char*)g_Bhi + (size_t)g * 16384;
    char* dlo = (char*)g_Blo + (size_t)g * 16384;
    const int k0 = kc*KCH, u0 = pass*256;
    const int ul = tid;
    for (int k4 = 0; k4 < 8; k4++) {
        float f[4];
        #pragma unroll
        for (int j = 0; j < 4; j++) f[j] = W1[(size_t)(k0 + k4*4 + j)*U + u0 + ul];
        unsigned short h[4], l[4];
        #pragma unroll
        for (int j = 0; j < 4; j++) {
            h[j] = bfbits(f[j]);
            __nv_bfloat16 hb = *reinterpret_cast<__nv_bfloat16*>(&h[j]);
            l[j] = bfbits(f[j] - __bfloat162float(hb));
        }
        uint32_t off = sw64((uint32_t)ul*64 + k4*8);
        *(uint2*)(dhi + off) = make_uint2((uint32_t)h[0] | ((uint32_t)h[1] << 16),
                                          (uint32_t)h[2] | ((uint32_t)h[3] << 16));
        *(uint2*)(dlo + off) = make_uint2((uint32_t)l[0] | ((uint32_t)l[1] << 16),
                                          (uint32_t)l[2] | ((uint32_t)l[3] << 16));
    }
#else
    const int k0 = blockIdx.x*32;
    const int u  = blockIdx.y*256 + tid;
    for (int k4 = 0; k4 < 8; k4++) {
        float f[4];
        #pragma unroll
        for (int j = 0; j < 4; j++) f[j] = W1[(size_t)(k0 + k4*4 + j)*U + u];
        unsigned short h[4], l[4];
        #pragma unroll
        for (int j = 0; j < 4; j++) {
            h[j] = bfbits(f[j]);
            __nv_bfloat16 hb = *reinterpret_cast<__nv_bfloat16*>(&h[j]);
            l[j] = bfbits(f[j] - __bfloat162float(hb));
        }
        *(uint2*)&g_Bhi[(size_t)u*WPAD + k0 + k4*4] =
            make_uint2((uint32_t)h[0] | ((uint32_t)h[1] << 16),
                       (uint32_t)h[2] | ((uint32_t)h[3] << 16));
        *(uint2*)&g_Blo[(size_t)u*WPAD + k0 + k4*4] =
            make_uint2((uint32_t)l[0] | ((uint32_t)l[1] << 16),
                       (uint32_t)l[2] | ((uint32_t)l[3] << 16));
    }
#endif
}

// ---------------------------------------------------------------------------
// Kernel 2b: values -> bf16 hi/lo A granules (tc layout), done ONCE.
// Grid (32 kc, 256 rowblocks), 256 threads. Granule = [256 r][32 k] SW64, 16 KB.
// ---------------------------------------------------------------------------
__global__ void __launch_bounds__(256)
a_convert_kernel(const float* __restrict__ values) {
    const int kc = blockIdx.x;       // 0..31
    const int rb = blockIdx.y;       // 0..255
    const int tid = threadIdx.x;
    char* dhi = (char*)g_Ahi + ((size_t)rb*32 + kc) * 16384;
    char* dlo = (char*)g_Alo + ((size_t)rb*32 + kc) * 16384;
    const float4* src = reinterpret_cast<const float4*>(values) + (size_t)rb*256*256 + kc*8;
    #pragma unroll
    for (int i = 0; i < 8; i++) {
        int idx = tid + 256*i;       // 0..2047
        int r = idx >> 3;
        int s = idx & 7;
        float4 v = src[(size_t)r*256 + s];
        float f[4] = {v.x, v.y, v.z, v.w};
        unsigned short h[4], l[4];
        #pragma unroll
        for (int j = 0; j < 4; j++) {
            h[j] = bfbits(f[j]);
            __nv_bfloat16 hb = *reinterpret_cast<__nv_bfloat16*>(&h[j]);
            l[j] = bfbits(f[j] - __bfloat162float(hb));
        }
        uint32_t off = sw64((uint32_t)r*64 + s*8);
        *(uint2*)(dhi + off) = make_uint2((uint32_t)h[0] | ((uint32_t)h[1] << 16),
                                          (uint32_t)h[2] | ((uint32_t)h[3] << 16));
        *(uint2*)(dlo + off) = make_uint2((uint32_t)l[0] | ((uint32_t)l[1] << 16),
                                          (uint32_t)l[2] | ((uint32_t)l[3] << 16));
    }
}

// ---------------------------------------------------------------------------
// Kernel 3a: tcgen05 score GEMM. 256 rows x 1024 u per CTA (256 CTAs).
// Pure bulk-copy + MMA pipeline (3 stages, tid0 drives; all mbarrier parity
// tracking is tid0-only — the driver serializes every flip, so no ABA).
// Other threads are released per-pass via __syncthreads().
// ---------------------------------------------------------------------------
#if HAS_TCGEN05
__device__ __forceinline__ void issue_copies(uint32_t sb, int rb, int g) {
    const int slot = g % 3;
    const uint32_t st = sb + OF_STG + slot*STG_BYTES;
    const uint32_t full = sb + OF_FULL + 8*slot;
    mbar_expect_tx(full, STG_BYTES);
    size_t aoff = ((size_t)rb*32 + (g & 31)) * 16384;
    size_t boff = (size_t)g * 16384;
    bulk_g2s(st + SOF_AHI, (const char*)g_Ahi + aoff, 16384, full);
    bulk_g2s(st + SOF_ALO, (const char*)g_Alo + aoff, 16384, full);
    bulk_g2s(st + SOF_BHI, (const char*)g_Bhi + boff, 16384, full);
    bulk_g2s(st + SOF_BLO, (const char*)g_Blo + boff, 16384, full);
}
#endif

__global__ void __launch_bounds__(NTHREADS, 1)
score_gemm_tc(const float* __restrict__ values, const float* __restrict__ Vv) {
#if HAS_TCGEN05
    const uint32_t raw = smem_u32(dynsmem);
    const uint32_t sb = (raw + 1023) & ~1023u;
    char* sbp = dynsmem + (sb - raw);

    const int tid = threadIdx.x;
    const int wid = tid >> 5;
    const int rb  = blockIdx.x;          // row block (256 rows)
    const int row0 = rb * GM;
    const int bidx = row0 / T;

    if (wid == 0) {
        tm_alloc(sb + OF_TM, 512);
        tm_relinquish();
    }
    if (tid == 0) {
        #pragma unroll
        for (int s = 0; s < 3; s++) {
            mbar_init(sb + OF_FULL + 8*s, 1);
            mbar_init(sb + OF_DONE + 8*s, 1);
        }
    }
    __syncthreads();
    const uint32_t tmem = *(volatile uint32_t*)(sbp + OF_TM);

    float score = 0.f;
    const int rt = wid >> 2;                 // epilogue row-tile

    if (tid == 0) {
        issue_copies(sb, rb, 0);
        issue_copies(sb, rb, 1);
        issue_copies(sb, rb, 2);
    }

    for (int pass = 0; pass < NPASS; pass++) {
        if (tid == 0) {
            tc_fence_after();   // order vs previous pass's thread-sync'd TMEM reads
            for (int c = 0; c < NKC; c++) {
                const int g = pass*NKC + c;
                const int slot = g % 3;
                mbar_wait(sb + OF_FULL + 8*slot, (uint32_t)((g/3) & 1));
                const uint32_t st = sb + OF_STG + slot*STG_BYTES;
                uint64_t adh = make_desc64(st + SOF_AHI);
                uint64_t adl = make_desc64(st + SOF_ALO);
                uint64_t bdh = make_desc64(st + SOF_BHI);
                uint64_t bdl = make_desc64(st + SOF_BLO);
                #pragma unroll
                for (int r2 = 0; r2 < 2; r2++) {
                    uint32_t dt = tmem + r2*256;
                    uint64_t art = (uint64_t)(r2*512);
                    #pragma unroll
                    for (int ks = 0; ks < 2; ks++) {
                        uint64_t ao = art + ks*2;
                        uint64_t bo = (uint64_t)(ks*2);
                        uint32_t en0 = (c > 0 || ks > 0) ? 1u : 0u;
                        mma_f16_ss(dt, adh + ao, bdh + bo, MMA_IDESC, en0);
                        mma_f16_ss(dt, adh + ao, bdl + bo, MMA_IDESC, 1u);
                        mma_f16_ss(dt, adl + ao, bdh + bo, MMA_IDESC, 1u);
                    }
                }
                tm_commit(sb + OF_DONE + 8*slot);
                // lookahead: free slot of chunk g-1, then copy chunk g+2 into it
                if (g >= 1 && g + 2 < NCH) {
                    const int gp = g - 1;
                    mbar_wait(sb + OF_DONE + 8*(gp % 3), (uint32_t)((gp/3) & 1));
                    issue_copies(sb, rb, g + 2);
                }
            }
            // driver-only wait for this pass's final chunk (ABA-safe: tid0
            // serializes all flips of this barrier)
            {
                const int gl = pass*NKC + (NKC - 1);
                mbar_wait(sb + OF_DONE + 8*(gl % 3), (uint32_t)((gl/3) & 1));
            }
        }
        __syncthreads();       // release all threads: pass MMAs complete
        tc_fence_after();      // order TMEM reads after the thread sync

        // epilogue: each thread owns row (row0 + tid); warp reads its subpartition
        {
            const uint32_t dbase = tmem + rt*256;
            const float* pqrow = &g_pq[bidx*U + pass*256];
            const float* vvrow = &Vv[pass*256];
            #pragma unroll
            for (int j = 0; j < 8; j++) {
                uint32_t r[32];
                TCLD32(r, dbase + j*32);
                tc_wait_ld();
                #pragma unroll
                for (int c2 = 0; c2 < 32; c2++) {
                    int u = j*32 + c2;
                    float dv = __uint_as_float(r[c2]);
                    score += fast_tanh(dv + pqrow[u]) * vvrow[u];
                }
            }
        }
        tc_fence_before();
        __syncthreads();   // D reads complete before next pass's en=0 MMA
    }

    g_score[row0 + tid] = score;

    __syncthreads();
    if (tid == 0) {
        #pragma unroll
        for (int s = 0; s < 3; s++) {
            mbar_inval(sb + OF_FULL + 8*s);
            mbar_inval(sb + OF_DONE + 8*s);
        }
    }
    __syncthreads();
    if (wid == 0) tm_dealloc(tmem, 512);
#endif  // HAS_TCGEN05
}

// ---------------------------------------------------------------------------
// Kernel 3b: fallback mma.sync (HMMA) score GEMM (body only on plain sm_103)
// ---------------------------------------------------------------------------
__global__ void __launch_bounds__(256)
score_gemm_mma(const float* __restrict__ values, const float* __restrict__ Vv) {
#if !HAS_TCGEN05
    const int tid  = threadIdx.x;
    const int wid  = tid >> 5;
    const int lane = tid & 31;
    const int row0 = blockIdx.x * 128;
    const int bidx = row0 / T;
    const int c = lane & 3;
    const int g = lane >> 2;

    __nv_bfloat16* As_hi = (__nv_bfloat16*)dynsmem;
    __nv_bfloat16* As_lo = As_hi + FB_TILE;
    __nv_bfloat16* Bs_hi = As_lo + FB_TILE;
    __nv_bfloat16* Bs_lo = Bs_hi + FB_TILE;
    const uint32_t smb   = smem_u32(dynsmem);
    const uint32_t ahi_b = smb;
    const uint32_t alo_b = smb + FB_TILE*2;
    const uint32_t bhi_b = smb + 2*FB_TILE*2;
    const uint32_t blo_b = smb + 3*FB_TILE*2;

    float score0 = 0.f, score1 = 0.f;

    for (int p = 0; p < FB_NP; p++) {
        const int u0 = p * 128;
        float acc[16][4];
        #pragma unroll
        for (int i = 0; i < 16; i++)
            #pragma unroll
            for (int j = 0; j < 4; j++) acc[i][j] = 0.f;

        for (int kc = 0; kc < FB_KC; kc++) {
            const int k0 = kc * 64;
            #pragma unroll
            for (int i = 0; i < 8; i++) {
                int idx = tid + 256*i;
                int r = idx >> 4;
                int s = idx & 15;
                float4 v = *(const float4*)&values[(size_t)(row0 + r)*D + k0 + s*4];
                float f[4] = {v.x, v.y, v.z, v.w};
                unsigned short h[4], l[4];
                #pragma unroll
                for (int j = 0; j < 4; j++) {
                    h[j] = bfbits(f[j]);
                    __nv_bfloat16 hb = *reinterpret_cast<__nv_bfloat16*>(&h[j]);
                    l[j] = bfbits(f[j] - __bfloat162float(hb));
                }
                *(uint2*)&As_hi[r*FB_STRIDE + s*4] =
                    make_uint2((uint32_t)h[0] | ((uint32_t)h[1] << 16),
                               (uint32_t)h[2] | ((uint32_t)h[3] << 16));
                *(uint2*)&As_lo[r*FB_STRIDE + s*4] =
                    make_uint2((uint32_t)l[0] | ((uint32_t)l[1] << 16),
                               (uint32_t)l[2] | ((uint32_t)l[3] << 16));
            }
            #pragma unroll
            for (int i = 0; i < 4; i++) {
                int idx = tid + 256*i;
                int n = idx >> 3;
                int m = idx & 7;
                *(uint4*)&Bs_hi[n*FB_STRIDE + m*8] =
                    *(const uint4*)&g_Bhi[(size_t)(u0 + n)*WPAD + k0 + m*8];
                *(uint4*)&Bs_lo[n*FB_STRIDE + m*8] =
                    *(const uint4*)&g_Blo[(size_t)(u0 + n)*WPAD + k0 + m*8];
            }
            __syncthreads();

            #pragma unroll
            for (int ks = 0; ks < 4; ks++) {
                uint32_t ah[4], al[4];
                uint32_t aoff = ((uint32_t)(16*wid + (lane & 15))*FB_STRIDE
                                 + ks*16 + ((lane >> 4) << 3)) * 2;
                ldsm_x4(ah[0], ah[1], ah[2], ah[3], ahi_b + aoff);
                ldsm_x4(al[0], al[1], al[2], al[3], alo_b + aoff);

                #pragma unroll
                for (int nt2 = 0; nt2 < 8; nt2++) {
                    int mtx = lane >> 3, r8 = lane & 7;
                    uint32_t n   = nt2*16 + ((mtx >> 1) << 3) + r8;
                    uint32_t kof = ks*16 + ((mtx & 1) << 3);
                    uint32_t boff = (n*FB_STRIDE + kof) * 2;
                    uint32_t bh0, bh1, bh2, bh3, bl0, bl1, bl2, bl3;
                    ldsm_x4(bh0, bh1, bh2, bh3, bhi_b + boff);
                    ldsm_x4(bl0, bl1, bl2, bl3, blo_b + boff);
                    mma16816(acc[2*nt2],     ah, bh0, bh1);
                    mma16816(acc[2*nt2],     ah, bl0, bl1);
                    mma16816(acc[2*nt2],     al, bh0, bh1);
                    mma16816(acc[2*nt2 + 1], ah, bh2, bh3);
                    mma16816(acc[2*nt2 + 1], ah, bl2, bl3);
                    mma16816(acc[2*nt2 + 1], al, bh2, bh3);
                }
            }
            __syncthreads();
        }

        #pragma unroll
        for (int nt = 0; nt < 16; nt++) {
            #pragma unroll
            for (int j = 0; j < 2; j++) {
                int u = u0 + nt*8 + 2*c + j;
                float pqv = g_pq[bidx*U + u];
                float vv  = Vv[u];
                score0 += tanhf(acc[nt][j]     + pqv) * vv;
                score1 += tanhf(acc[nt][2 + j] + pqv) * vv;
            }
        }
    }

    score0 += __shfl_xor_sync(0xffffffffu, score0, 1);
    score0 += __shfl_xor_sync(0xffffffffu, score0, 2);
    score1 += __shfl_xor_sync(0xffffffffu, score1, 1);
    score1 += __shfl_xor_sync(0xffffffffu, score1, 2);
    if (c == 0) {
        g_score[row0 + wid*16 + g]     = score0;
        g_score[row0 + wid*16 + 8 + g] = score1;
    }
#endif  // !HAS_TCGEN05
}

// ---------------------------------------------------------------------------
// Kernel 4: mask + softmax over T -> attention weights
// ---------------------------------------------------------------------------
__global__ void softmax_kernel(const float* __restrict__ mask,
                               const float* __restrict__ bV,
                               float* __restrict__ attn) {
    const int b = blockIdx.x;
    __shared__ float sc[T];
    __shared__ float redbuf[256];
    const float bv = bV[0];

    for (int t = threadIdx.x; t < T; t += 256)
        sc[t] = g_score[b*T + t] + bv + mask[b*T + t] * (-1e9f);
    __syncthreads();

    float m = -INFINITY;
    for (int t = threadIdx.x; t < T; t += 256) m = fmaxf(m, sc[t]);
    redbuf[threadIdx.x] = m;
    __syncthreads();
    for (int s = 128; s > 0; s >>= 1) {
        if (threadIdx.x < s) redbuf[threadIdx.x] = fmaxf(redbuf[threadIdx.x], redbuf[threadIdx.x + s]);
        __syncthreads();
    }
    m = redbuf[0];
    __syncthreads();

    float sum = 0.f;
    for (int t = threadIdx.x; t < T; t += 256) {
        float e = expf(sc[t] - m);
        sc[t] = e;
        sum += e;
    }
    redbuf[threadIdx.x] = sum;
    __syncthreads();
    for (int s = 128; s > 0; s >>= 1) {
        if (threadIdx.x < s) redbuf[threadIdx.x] += redbuf[threadIdx.x + s];
        __syncthreads();
    }
    const float inv = 1.f / redbuf[0];
    __syncthreads();

    for (int t = threadIdx.x; t < T; t += 256) attn[b*T + t] = sc[t] * inv;
}

// ---------------------------------------------------------------------------
// Kernel 5/6: context = sum_t attn * values
// ---------------------------------------------------------------------------
__global__ void __launch_bounds__(256)
context_partial_kernel(const float* __restrict__ values,
                       const float* __restrict__ attn) {
    const int ts = blockIdx.x;
    const int b  = blockIdx.y;
    const int t0 = ts * (T / TS);
    const int tid = threadIdx.x;

    __shared__ float w[T / TS];
    if (tid < T / TS) w[tid] = attn[b*T + t0 + tid];
    __syncthreads();

    const float4* vp = (const float4*)(values + ((size_t)b*T + t0) * D) + tid;
    float4 acc = make_float4(0.f, 0.f, 0.f, 0.f);
    #pragma unroll 4
    for (int t = 0; t < T / TS; t++) {
        float4 v = vp[(size_t)t * (D/4)];
        float wt = w[t];
        acc.x += wt * v.x; acc.y += wt * v.y;
        acc.z += wt * v.z; acc.w += wt * v.w;
    }
    ((float4*)(g_ctxp + ((size_t)ts*B + b) * D))[tid] = acc;
}

__global__ void context_reduce_kernel(float* __restrict__ ctx) {
    int i = blockIdx.x * 256 + threadIdx.x;
    float s = 0.f;
    #pragma unroll
    for (int p = 0; p < TS; p++) s += g_ctxp[(size_t)p*B*D + i];
    ctx[i] = s;
}

// ---------------------------------------------------------------------------
extern "C" void kernel_launch(void* const* d_in, const int* in_sizes, int n_in,
                              void* d_out, int out_size) {
    const float* values = (const float*)d_in[0];
    const float* query  = (const float*)d_in[1];
    const float* mask   = (const float*)d_in[2];
    const float* W1     = (const float*)d_in[3];
    const float* b1     = (const float*)d_in[4];
    const float* W2     = (const float*)d_in[5];
    const float* b2     = (const float*)d_in[6];
    const float* Vv     = (const float*)d_in[7];
    const float* bV     = (const float*)d_in[8];

    float* ctx  = (float*)d_out;
    float* attn = (float*)d_out + B*D;

    cudaFuncSetAttribute(score_gemm_tc,  cudaFuncAttributeMaxDynamicSharedMemorySize, SMEM_BYTES);
    cudaFuncSetAttribute(score_gemm_mma, cudaFuncAttributeMaxDynamicSharedMemorySize, FB_SMEM);

    pq_kernel<<<B, 256>>>(query, W2, b1, b2);
    w1_convert_kernel<<<dim3(32, 4), 256>>>(W1);
    a_convert_kernel<<<dim3(32, 256), 256>>>(values);

    // Exactly one of these has a body (compile-time arch feature selection).
    score_gemm_tc <<<NROWS/GM, NTHREADS, SMEM_BYTES>>>(values, Vv);
    score_gemm_mma<<<NROWS/128, 256, FB_SMEM>>>(values, Vv);

    softmax_kernel<<<B, 256>>>(mask, bV, attn);
    dim3 cgrid(TS, B);
    context_partial_kernel<<<cgrid, 256>>>(values, attn);
    context_reduce_kernel<<<(B*D)/256, 256>>>(ctx);
}

// round 7
// speedup vs baseline: 6.3362x; 1.0762x over previous
#include <cuda_runtime.h>
#include <cuda_bf16.h>
#include <math.h>
#include <stdint.h>

// Problem constants
#define B 32
#define T 2048
#define D 1024
#define U 1024
#define NROWS (B*T)          // 65536
#define TS 16                // context t-splits

#if defined(__CUDA_ARCH_FEAT_SM103_ALL) || defined(__CUDA_ARCH_FEAT_SM100_ALL)
#define HAS_TCGEN05 1
#else
#define HAS_TCGEN05 0
#endif

// tcgen05 GEMM config: 128 rows/CTA (512 CTAs), N=256 per pass, 4 passes,
// k-chunks of 32 (2 k-steps), SW64, TMEM ping-pong (pass p -> cols (p&1)*256),
// 4-stage cp.async.bulk pipeline, warp-specialized (tid0 driver, warps 4-7 epilogue).
#define GM 128
#define KCH 32
#define NKC 32               // chunks per pass (D/KCH)
#define NPASS 4
#define NCH 128              // total chunks
#define NTHREADS 256

// idesc: dtype=F32(1<<4), atype=BF16(1<<7), btype=BF16(1<<10), N/8<<17, M/16<<24
// M=128 per MMA -> 8<<24 ; N=256 -> 32<<17
#define MMA_IDESC ((8u<<24) | (32u<<17) | (1u<<10) | (1u<<7) | (1u<<4))

// SMEM layout (offsets from 1024-aligned base)
#define OF_TM    0u
#define OF_FULL  16u             // 4 mbarriers @16..47
#define OF_DONE  48u             // 4 mbarriers @48..79
#define OF_PDONE 80u             // 2 mbarriers @80..95  (pass MMAs complete)
#define OF_EPI   96u             // 2 mbarriers @96..111 (epilogue reads complete, cnt=128)
#define OF_PQ    1024u           // 4 KB pq row for this batch
#define OF_VV    5120u           // 4 KB V
#define OF_STG   9216u           // 4 stages x 49152
#define SOF_AHI  0u              // 8 KB
#define SOF_ALO  8192u           // 8 KB
#define SOF_BHI  16384u          // 16 KB
#define SOF_BLO  32768u          // 16 KB
#define STG_BYTES 49152u
#define SMEM_BYTES (9216 + 4*49152 + 1024)

// fallback (mma.sync) config — unchanged
#define FB_NP   8
#define FB_KC   16
#define FB_STRIDE 72
#define FB_TILE (128*FB_STRIDE)
#define FB_SMEM (4*FB_TILE*2)
#define WPAD (D+8)

// Scratch (device globals; no allocation allowed)
__device__ float g_pq[B*U];
__device__ float g_score[NROWS];
__device__ float g_ctxp[TS*B*D];
// tc: A granules [512 rowblocks][32 kc][8KB SW64 (128r x 32k)]
__device__ __align__(16) __nv_bfloat16 g_Ahi[NROWS*D];   // 128 MB
__device__ __align__(16) __nv_bfloat16 g_Alo[NROWS*D];   // 128 MB
// tc: B granules [4 pass][32 kc][16KB SW64 (256u x 32k)]; fallback: [U][WPAD]
__device__ __align__(16) __nv_bfloat16 g_Bhi[U*WPAD];
__device__ __align__(16) __nv_bfloat16 g_Blo[U*WPAD];

// ---------------------------------------------------------------------------
// Common helpers
// ---------------------------------------------------------------------------
__device__ __forceinline__ uint32_t smem_u32(const void* p) {
    uint32_t a;
    asm("{ .reg .u64 t; cvta.to.shared.u64 t, %1; cvt.u32.u64 %0, t; }" : "=r"(a) : "l"(p));
    return a;
}
__device__ __host__ __forceinline__ uint32_t sw64(uint32_t o) { return o ^ ((o >> 3) & 0x30); }

__device__ __forceinline__ unsigned short bfbits(float v) {
    __nv_bfloat16 b = __float2bfloat16(v);
    return *reinterpret_cast<unsigned short*>(&b);
}
__device__ __forceinline__ float fast_tanh(float x) {
    float ax = fabsf(x);
    float e = __expf(ax + ax);
    float t = 1.0f - __fdividef(2.0f, e + 1.0f);
    return copysignf(t, x);
}

extern __shared__ char dynsmem[];

#if HAS_TCGEN05
__device__ __forceinline__ void tm_alloc(uint32_t smem_dst, uint32_t ncols) {
    asm volatile("tcgen05.alloc.cta_group::1.sync.aligned.shared::cta.b32 [%0], %1;"
                 :: "r"(smem_dst), "r"(ncols) : "memory");
}
__device__ __forceinline__ void tm_relinquish() {
    asm volatile("tcgen05.relinquish_alloc_permit.cta_group::1.sync.aligned;");
}
__device__ __forceinline__ void tm_dealloc(uint32_t tmem, uint32_t ncols) {
    asm volatile("tcgen05.dealloc.cta_group::1.sync.aligned.b32 %0, %1;" :: "r"(tmem), "r"(ncols));
}
__device__ __forceinline__ void mma_f16_ss(uint32_t d_tmem, uint64_t a_desc, uint64_t b_desc,
                                           uint32_t idesc, uint32_t en) {
    asm volatile("{\n\t.reg .pred p;\n\t"
                 "setp.ne.u32 p, %5, 0;\n\t"
                 "tcgen05.mma.cta_group::1.kind::f16 [%0], %1, %2, %3, {%4, %4, %4, %4}, p;\n\t}"
                 :: "r"(d_tmem), "l"(a_desc), "l"(b_desc), "r"(idesc), "r"(0u), "r"(en)
                 : "memory");
}
__device__ __forceinline__ void tm_commit(uint32_t mbar) {
    asm volatile("tcgen05.commit.cta_group::1.mbarrier::arrive::one.shared::cluster.b64 [%0];"
                 :: "r"(mbar) : "memory");
}
__device__ __forceinline__ void tc_fence_after() {
    asm volatile("tcgen05.fence::after_thread_sync;" ::: "memory");
}
__device__ __forceinline__ void tc_fence_before() {
    asm volatile("tcgen05.fence::before_thread_sync;" ::: "memory");
}
__device__ __forceinline__ void tc_wait_ld() {
    asm volatile("tcgen05.wait::ld.sync.aligned;" ::: "memory");
}
#define TCLD32(r, a) \
    asm volatile("tcgen05.ld.sync.aligned.32x32b.x32.b32 " \
        "{%0, %1, %2, %3, %4, %5, %6, %7, %8, %9, %10, %11, %12, %13, %14, %15, " \
        " %16, %17, %18, %19, %20, %21, %22, %23, %24, %25, %26, %27, %28, %29, %30, %31}, [%32];" \
        : "=r"((r)[0]),  "=r"((r)[1]),  "=r"((r)[2]),  "=r"((r)[3]), \
          "=r"((r)[4]),  "=r"((r)[5]),  "=r"((r)[6]),  "=r"((r)[7]), \
          "=r"((r)[8]),  "=r"((r)[9]),  "=r"((r)[10]), "=r"((r)[11]), \
          "=r"((r)[12]), "=r"((r)[13]), "=r"((r)[14]), "=r"((r)[15]), \
          "=r"((r)[16]), "=r"((r)[17]), "=r"((r)[18]), "=r"((r)[19]), \
          "=r"((r)[20]), "=r"((r)[21]), "=r"((r)[22]), "=r"((r)[23]), \
          "=r"((r)[24]), "=r"((r)[25]), "=r"((r)[26]), "=r"((r)[27]), \
          "=r"((r)[28]), "=r"((r)[29]), "=r"((r)[30]), "=r"((r)[31]) \
        : "r"(a))
// SW64 descriptor: layout_type=4, version=1, SBO=32 (512B = 8 rows x 64B), LBO=1
__device__ __forceinline__ uint64_t make_desc64(uint32_t addr) {
    const uint64_t base = (uint64_t(4) << 61) | (uint64_t(1) << 46) |
                          (uint64_t(32) << 32) | (uint64_t(1) << 16);
    return base | ((uint64_t)(addr >> 4) & 0x3FFF);
}
__device__ __forceinline__ void bulk_g2s(uint32_t dst, const void* src, uint32_t bytes, uint32_t mbar) {
    asm volatile("cp.async.bulk.shared::cluster.global.mbarrier::complete_tx::bytes [%0], [%1], %2, [%3];"
                 :: "r"(dst), "l"(src), "r"(bytes), "r"(mbar) : "memory");
}
__device__ __forceinline__ void mbar_expect_tx(uint32_t a, uint32_t bytes) {
    asm volatile("mbarrier.arrive.expect_tx.shared.b64 _, [%0], %1;" :: "r"(a), "r"(bytes) : "memory");
}
#endif  // HAS_TCGEN05

__device__ __forceinline__ void mbar_init(uint32_t a, uint32_t cnt) {
    asm volatile("mbarrier.init.shared.b64 [%0], %1;" :: "r"(a), "r"(cnt) : "memory");
}
__device__ __forceinline__ void mbar_inval(uint32_t a) {
    asm volatile("mbarrier.inval.shared.b64 [%0];" :: "r"(a) : "memory");
}
__device__ __forceinline__ void mbar_arrive(uint32_t a) {
    asm volatile("mbarrier.arrive.shared.b64 _, [%0];" :: "r"(a) : "memory");
}
__device__ __forceinline__ void mbar_wait(uint32_t a, uint32_t parity) {
    uint32_t done;
    asm volatile("{\n\t.reg .pred p;\n\t"
                 "mbarrier.try_wait.parity.acquire.cta.shared::cta.b64 p, [%1], %2;\n\t"
                 "selp.b32 %0, 1, 0, p;\n\t}"
                 : "=r"(done) : "r"(a), "r"(parity) : "memory");
    if (!done) {
        asm volatile("{\n\t.reg .pred P1;\n\t"
                     "WL_%=:\n\t"
                     "mbarrier.try_wait.parity.acquire.cta.shared::cta.b64 P1, [%0], %1, 0x989680;\n\t"
                     "@P1 bra.uni WD_%=;\n\t"
                     "bra.uni WL_%=;\n\t"
                     "WD_%=:\n\t}"
                     :: "r"(a), "r"(parity) : "memory");
    }
}

// ---------------------------------------------------------------------------
// Fallback (mma.sync) helpers — legal on plain compute_103
// ---------------------------------------------------------------------------
__device__ __forceinline__ void ldsm_x4(uint32_t& r0, uint32_t& r1, uint32_t& r2, uint32_t& r3,
                                        uint32_t addr) {
    asm volatile("ldmatrix.sync.aligned.m8n8.x4.shared.b16 {%0,%1,%2,%3}, [%4];"
                 : "=r"(r0), "=r"(r1), "=r"(r2), "=r"(r3) : "r"(addr));
}
__device__ __forceinline__ void mma16816(float* d, const uint32_t* a, uint32_t b0, uint32_t b1) {
    asm volatile("mma.sync.aligned.m16n8k16.row.col.f32.bf16.bf16.f32 "
                 "{%0,%1,%2,%3}, {%4,%5,%6,%7}, {%8,%9}, {%0,%1,%2,%3};"
                 : "+f"(d[0]), "+f"(d[1]), "+f"(d[2]), "+f"(d[3])
                 : "r"(a[0]), "r"(a[1]), "r"(a[2]), "r"(a[3]), "r"(b0), "r"(b1));
}

// ---------------------------------------------------------------------------
// Kernel 1 (merged prep): blocks [0,8192) = A convert; [8192,8320) = W1
// convert; [8320,8352) = pq. All three are independent; one launch fills the
// chip instead of three serial launches.
// ---------------------------------------------------------------------------
__global__ void __launch_bounds__(256)
prep_kernel(const float* __restrict__ values, const float* __restrict__ W1,
            const float* __restrict__ query, const float* __restrict__ W2,
            const float* __restrict__ b1, const float* __restrict__ b2) {
    const int blk = blockIdx.x;
    const int tid = threadIdx.x;
    __shared__ float q[D];

    if (blk < 8192) {
#if HAS_TCGEN05
        // A convert: 256 rows (2 rowblocks of 128) x 32 k per block
        const int kc  = blk & 31;
        const int rbp = blk >> 5;            // 0..255
        const float4* src = reinterpret_cast<const float4*>(values)
                            + (size_t)rbp*256*256 + kc*8;
        #pragma unroll
        for (int i = 0; i < 8; i++) {
            int idx = tid + 256*i;           // 0..2047
            int r = idx >> 3;                // 0..255
            int s = idx & 7;
            float4 v = src[(size_t)r*256 + s];
            float f[4] = {v.x, v.y, v.z, v.w};
            unsigned short h[4], l[4];
            #pragma unroll
            for (int j = 0; j < 4; j++) {
                h[j] = bfbits(f[j]);
                __nv_bfloat16 hb = *reinterpret_cast<__nv_bfloat16*>(&h[j]);
                l[j] = bfbits(f[j] - __bfloat162float(hb));
            }
            int rbg = rbp*2 + (r >> 7);      // rowblock of 128
            size_t gb = ((size_t)rbg*32 + kc) * 8192;
            uint32_t off = sw64((uint32_t)(r & 127)*64 + s*8);
            *(uint2*)((char*)g_Ahi + gb + off) =
                make_uint2((uint32_t)h[0] | ((uint32_t)h[1] << 16),
                           (uint32_t)h[2] | ((uint32_t)h[3] << 16));
            *(uint2*)((char*)g_Alo + gb + off) =
                make_uint2((uint32_t)l[0] | ((uint32_t)l[1] << 16),
                           (uint32_t)l[2] | ((uint32_t)l[3] << 16));
        }
#endif
    } else if (blk < 8320) {
        const int g2 = blk - 8192;           // 0..127 = pass*32 + kc
#if HAS_TCGEN05
        const int pass = g2 >> 5;
        const int kc = g2 & 31;
        char* dhi = (char*)g_Bhi + (size_t)g2 * 16384;
        char* dlo = (char*)g_Blo + (size_t)g2 * 16384;
        const int k0 = kc*KCH, u0 = pass*256;
        const int ul = tid;
        for (int k4 = 0; k4 < 8; k4++) {
            float f[4];
            #pragma unroll
            for (int j = 0; j < 4; j++) f[j] = W1[(size_t)(k0 + k4*4 + j)*U + u0 + ul];
            unsigned short h[4], l[4];
            #pragma unroll
            for (int j = 0; j < 4; j++) {
                h[j] = bfbits(f[j]);
                __nv_bfloat16 hb = *reinterpret_cast<__nv_bfloat16*>(&h[j]);
                l[j] = bfbits(f[j] - __bfloat162float(hb));
            }
            uint32_t off = sw64((uint32_t)ul*64 + k4*8);
            *(uint2*)(dhi + off) = make_uint2((uint32_t)h[0] | ((uint32_t)h[1] << 16),
                                              (uint32_t)h[2] | ((uint32_t)h[3] << 16));
            *(uint2*)(dlo + off) = make_uint2((uint32_t)l[0] | ((uint32_t)l[1] << 16),
                                              (uint32_t)l[2] | ((uint32_t)l[3] << 16));
        }
#else
        const int k0 = (g2 & 31)*32;
        const int u  = (g2 >> 5)*256 + tid;
        for (int k4 = 0; k4 < 8; k4++) {
            float f[4];
            #pragma unroll
            for (int j = 0; j < 4; j++) f[j] = W1[(size_t)(k0 + k4*4 + j)*U + u];
            unsigned short h[4], l[4];
            #pragma unroll
            for (int j = 0; j < 4; j++) {
                h[j] = bfbits(f[j]);
                __nv_bfloat16 hb = *reinterpret_cast<__nv_bfloat16*>(&h[j]);
                l[j] = bfbits(f[j] - __bfloat162float(hb));
            }
            *(uint2*)&g_Bhi[(size_t)u*WPAD + k0 + k4*4] =
                make_uint2((uint32_t)h[0] | ((uint32_t)h[1] << 16),
                           (uint32_t)h[2] | ((uint32_t)h[3] << 16));
            *(uint2*)&g_Blo[(size_t)u*WPAD + k0 + k4*4] =
                make_uint2((uint32_t)l[0] | ((uint32_t)l[1] << 16),
                           (uint32_t)l[2] | ((uint32_t)l[3] << 16));
        }
#endif
    } else {
        // pq: one block per batch
        const int b = blk - 8320;
        for (int i = tid; i < D; i += 256) q[i] = query[b*D + i];
        __syncthreads();
        int u = tid;
        float a0 = 0.f, a1 = 0.f, a2 = 0.f, a3 = 0.f;
        for (int d = 0; d < D; d++) {
            float qd = q[d];
            const float* w = &W2[(size_t)d*U + u];
            a0 += qd * w[0];   a1 += qd * w[256];
            a2 += qd * w[512]; a3 += qd * w[768];
        }
        g_pq[b*U + u      ] = a0 + b1[u      ] + b2[u      ];
        g_pq[b*U + u + 256] = a1 + b1[u + 256] + b2[u + 256];
        g_pq[b*U + u + 512] = a2 + b1[u + 512] + b2[u + 512];
        g_pq[b*U + u + 768] = a3 + b1[u + 768] + b2[u + 768];
    }
}

// ---------------------------------------------------------------------------
// Kernel 2a: tcgen05 score GEMM with TMEM ping-pong.
// 128 rows x 1024 u per CTA (512 CTAs). Pass p accumulates into TMEM cols
// (p&1)*256 so pass p's epilogue (warps 4-7) overlaps pass p+1's MMAs (tid0).
// ---------------------------------------------------------------------------
#if HAS_TCGEN05
__device__ __forceinline__ void issue_copies(uint32_t sb, int rb, int g) {
    const int slot = g & 3;
    const uint32_t st = sb + OF_STG + slot*STG_BYTES;
    const uint32_t full = sb + OF_FULL + 8*slot;
    mbar_expect_tx(full, STG_BYTES);
    size_t aoff = ((size_t)rb*32 + (g & 31)) * 8192;
    size_t boff = (size_t)g * 16384;
    bulk_g2s(st + SOF_AHI, (const char*)g_Ahi + aoff,  8192, full);
    bulk_g2s(st + SOF_ALO, (const char*)g_Alo + aoff,  8192, full);
    bulk_g2s(st + SOF_BHI, (const char*)g_Bhi + boff, 16384, full);
    bulk_g2s(st + SOF_BLO, (const char*)g_Blo + boff, 16384, full);
}
#endif

__global__ void __launch_bounds__(NTHREADS, 1)
score_gemm_tc(const float* __restrict__ values, const float* __restrict__ Vv) {
#if HAS_TCGEN05
    const uint32_t raw = smem_u32(dynsmem);
    const uint32_t sb = (raw + 1023) & ~1023u;
    char* sbp = dynsmem + (sb - raw);

    const int tid = threadIdx.x;
    const int wid = tid >> 5;
    const int lane = tid & 31;
    const int rb  = blockIdx.x;          // row block (128 rows)
    const int row0 = rb * GM;
    const int bidx = row0 / T;

    if (wid == 0) {
        tm_alloc(sb + OF_TM, 512);
        tm_relinquish();
    }
    if (tid == 0) {
        #pragma unroll
        for (int s = 0; s < 4; s++) {
            mbar_init(sb + OF_FULL + 8*s, 1);
            mbar_init(sb + OF_DONE + 8*s, 1);
        }
        mbar_init(sb + OF_PDONE,     1);
        mbar_init(sb + OF_PDONE + 8, 1);
        mbar_init(sb + OF_EPI,     128);
        mbar_init(sb + OF_EPI + 8, 128);
    }
    // preload pq row + V into SMEM (256 float4 each)
    {
        ((float4*)(sbp + OF_PQ))[tid] = ((const float4*)(g_pq + bidx*U))[tid];
        ((float4*)(sbp + OF_VV))[tid] = ((const float4*)Vv)[tid];
    }
    __syncthreads();
    const uint32_t tmem = *(volatile uint32_t*)(sbp + OF_TM);

    if (tid == 0) {
        // ---------------- driver ----------------
        tc_fence_after();
        issue_copies(sb, rb, 0);
        issue_copies(sb, rb, 1);
        issue_copies(sb, rb, 2);
        issue_copies(sb, rb, 3);
        for (int p = 0; p < NPASS; p++) {
            if (p >= 2) {                         // cols (p&1) must be drained
                mbar_wait(sb + OF_EPI + 8*(p & 1), 0);
                tc_fence_after();
            }
            const uint32_t dt = tmem + (p & 1)*256;
            for (int c = 0; c < NKC; c++) {
                const int g = p*NKC + c;
                const int slot = g & 3;
                mbar_wait(sb + OF_FULL + 8*slot, (uint32_t)((g >> 2) & 1));
                const uint32_t st = sb + OF_STG + slot*STG_BYTES;
                uint64_t adh = make_desc64(st + SOF_AHI);
                uint64_t adl = make_desc64(st + SOF_ALO);
                uint64_t bdh = make_desc64(st + SOF_BHI);
                uint64_t bdl = make_desc64(st + SOF_BLO);
                #pragma unroll
                for (int ks = 0; ks < 2; ks++) {
                    uint64_t o = (uint64_t)(ks*2);
                    uint32_t en0 = (c > 0 || ks > 0) ? 1u : 0u;
                    mma_f16_ss(dt, adh + o, bdh + o, MMA_IDESC, en0);
                    mma_f16_ss(dt, adh + o, bdl + o, MMA_IDESC, 1u);
                    mma_f16_ss(dt, adl + o, bdh + o, MMA_IDESC, 1u);
                }
                tm_commit(sb + OF_DONE + 8*slot);
                if (g >= 1 && g + 3 < NCH) {
                    const int gp = g - 1;
                    mbar_wait(sb + OF_DONE + 8*(gp & 3), (uint32_t)((gp >> 2) & 1));
                    issue_copies(sb, rb, g + 3);
                }
            }
            tm_commit(sb + OF_PDONE + 8*(p & 1));  // pass-complete signal
        }
    } else if (wid >= 4) {
        // ---------------- epilogue warps (rows (wid-4)*32+lane) ----------------
        float score = 0.f;
        const int myrow = (wid - 4)*32 + lane;
        const float* pqs = (const float*)(sbp + OF_PQ);
        const float* vvs = (const float*)(sbp + OF_VV);
        for (int p = 0; p < NPASS; p++) {
            mbar_wait(sb + OF_PDONE + 8*(p & 1), (uint32_t)((p >> 1) & 1));
            tc_fence_after();
            const uint32_t dbase = tmem + (p & 1)*256;
            #pragma unroll
            for (int j = 0; j < 8; j++) {
                uint32_t r[32];
                TCLD32(r, dbase + j*32);
                tc_wait_ld();
                #pragma unroll
                for (int c2 = 0; c2 < 32; c2++) {
                    int u = p*256 + j*32 + c2;
                    float dv = __uint_as_float(r[c2]);
                    score += fast_tanh(dv + pqs[u]) * vvs[u];
                }
            }
            tc_fence_before();
            mbar_arrive(sb + OF_EPI + 8*(p & 1));
        }
        g_score[row0 + myrow] = score;
    }
    // warps 1-3 fall through to here
    __syncthreads();
    if (tid == 0) {
        #pragma unroll
        for (int s = 0; s < 4; s++) {
            mbar_inval(sb + OF_FULL + 8*s);
            mbar_inval(sb + OF_DONE + 8*s);
        }
        mbar_inval(sb + OF_PDONE); mbar_inval(sb + OF_PDONE + 8);
        mbar_inval(sb + OF_EPI);   mbar_inval(sb + OF_EPI + 8);
    }
    __syncthreads();
    if (wid == 0) tm_dealloc(tmem, 512);
#endif  // HAS_TCGEN05
}

// ---------------------------------------------------------------------------
// Kernel 2b: fallback mma.sync (HMMA) score GEMM (body only on plain sm_103)
// ---------------------------------------------------------------------------
__global__ void __launch_bounds__(256)
score_gemm_mma(const float* __restrict__ values, const float* __restrict__ Vv) {
#if !HAS_TCGEN05
    const int tid  = threadIdx.x;
    const int wid  = tid >> 5;
    const int lane = tid & 31;
    const int row0 = blockIdx.x * 128;
    const int bidx = row0 / T;
    const int c = lane & 3;
    const int g = lane >> 2;

    __nv_bfloat16* As_hi = (__nv_bfloat16*)dynsmem;
    __nv_bfloat16* As_lo = As_hi + FB_TILE;
    __nv_bfloat16* Bs_hi = As_lo + FB_TILE;
    __nv_bfloat16* Bs_lo = Bs_hi + FB_TILE;
    const uint32_t smb   = smem_u32(dynsmem);
    const uint32_t ahi_b = smb;
    const uint32_t alo_b = smb + FB_TILE*2;
    const uint32_t bhi_b = smb + 2*FB_TILE*2;
    const uint32_t blo_b = smb + 3*FB_TILE*2;

    float score0 = 0.f, score1 = 0.f;

    for (int p = 0; p < FB_NP; p++) {
        const int u0 = p * 128;
        float acc[16][4];
        #pragma unroll
        for (int i = 0; i < 16; i++)
            #pragma unroll
            for (int j = 0; j < 4; j++) acc[i][j] = 0.f;

        for (int kc = 0; kc < FB_KC; kc++) {
            const int k0 = kc * 64;
            #pragma unroll
            for (int i = 0; i < 8; i++) {
                int idx = tid + 256*i;
                int r = idx >> 4;
                int s = idx & 15;
                float4 v = *(const float4*)&values[(size_t)(row0 + r)*D + k0 + s*4];
                float f[4] = {v.x, v.y, v.z, v.w};
                unsigned short h[4], l[4];
                #pragma unroll
                for (int j = 0; j < 4; j++) {
                    h[j] = bfbits(f[j]);
                    __nv_bfloat16 hb = *reinterpret_cast<__nv_bfloat16*>(&h[j]);
                    l[j] = bfbits(f[j] - __bfloat162float(hb));
                }
                *(uint2*)&As_hi[r*FB_STRIDE + s*4] =
                    make_uint2((uint32_t)h[0] | ((uint32_t)h[1] << 16),
                               (uint32_t)h[2] | ((uint32_t)h[3] << 16));
                *(uint2*)&As_lo[r*FB_STRIDE + s*4] =
                    make_uint2((uint32_t)l[0] | ((uint32_t)l[1] << 16),
                               (uint32_t)l[2] | ((uint32_t)l[3] << 16));
            }
            #pragma unroll
            for (int i = 0; i < 4; i++) {
                int idx = tid + 256*i;
                int n = idx >> 3;
                int m = idx & 7;
                *(uint4*)&Bs_hi[n*FB_STRIDE + m*8] =
                    *(const uint4*)&g_Bhi[(size_t)(u0 + n)*WPAD + k0 + m*8];
                *(uint4*)&Bs_lo[n*FB_STRIDE + m*8] =
                    *(const uint4*)&g_Blo[(size_t)(u0 + n)*WPAD + k0 + m*8];
            }
            __syncthreads();

            #pragma unroll
            for (int ks = 0; ks < 4; ks++) {
                uint32_t ah[4], al[4];
                uint32_t aoff = ((uint32_t)(16*wid + (lane & 15))*FB_STRIDE
                                 + ks*16 + ((lane >> 4) << 3)) * 2;
                ldsm_x4(ah[0], ah[1], ah[2], ah[3], ahi_b + aoff);
                ldsm_x4(al[0], al[1], al[2], al[3], alo_b + aoff);

                #pragma unroll
                for (int nt2 = 0; nt2 < 8; nt2++) {
                    int mtx = lane >> 3, r8 = lane & 7;
                    uint32_t n   = nt2*16 + ((mtx >> 1) << 3) + r8;
                    uint32_t kof = ks*16 + ((mtx & 1) << 3);
                    uint32_t boff = (n*FB_STRIDE + kof) * 2;
                    uint32_t bh0, bh1, bh2, bh3, bl0, bl1, bl2, bl3;
                    ldsm_x4(bh0, bh1, bh2, bh3, bhi_b + boff);
                    ldsm_x4(bl0, bl1, bl2, bl3, blo_b + boff);
                    mma16816(acc[2*nt2],     ah, bh0, bh1);
                    mma16816(acc[2*nt2],     ah, bl0, bl1);
                    mma16816(acc[2*nt2],     al, bh0, bh1);
                    mma16816(acc[2*nt2 + 1], ah, bh2, bh3);
                    mma16816(acc[2*nt2 + 1], ah, bl2, bl3);
                    mma16816(acc[2*nt2 + 1], al, bh2, bh3);
                }
            }
            __syncthreads();
        }

        #pragma unroll
        for (int nt = 0; nt < 16; nt++) {
            #pragma unroll
            for (int j = 0; j < 2; j++) {
                int u = u0 + nt*8 + 2*c + j;
                float pqv = g_pq[bidx*U + u];
                float vv  = Vv[u];
                score0 += tanhf(acc[nt][j]     + pqv) * vv;
                score1 += tanhf(acc[nt][2 + j] + pqv) * vv;
            }
        }
    }

    score0 += __shfl_xor_sync(0xffffffffu, score0, 1);
    score0 += __shfl_xor_sync(0xffffffffu, score0, 2);
    score1 += __shfl_xor_sync(0xffffffffu, score1, 1);
    score1 += __shfl_xor_sync(0xffffffffu, score1, 2);
    if (c == 0) {
        g_score[row0 + wid*16 + g]     = score0;
        g_score[row0 + wid*16 + 8 + g] = score1;
    }
#endif  // !HAS_TCGEN05
}

// ---------------------------------------------------------------------------
// Kernel 3: mask + softmax over T -> attention weights
// ---------------------------------------------------------------------------
__global__ void softmax_kernel(const float* __restrict__ mask,
                               const float* __restrict__ bV,
                               float* __restrict__ attn) {
    const int b = blockIdx.x;
    __shared__ float sc[T];
    __shared__ float redbuf[256];
    const float bv = bV[0];

    for (int t = threadIdx.x; t < T; t += 256)
        sc[t] = g_score[b*T + t] + bv + mask[b*T + t] * (-1e9f);
    __syncthreads();

    float m = -INFINITY;
    for (int t = threadIdx.x; t < T; t += 256) m = fmaxf(m, sc[t]);
    redbuf[threadIdx.x] = m;
    __syncthreads();
    for (int s = 128; s > 0; s >>= 1) {
        if (threadIdx.x < s) redbuf[threadIdx.x] = fmaxf(redbuf[threadIdx.x], redbuf[threadIdx.x + s]);
        __syncthreads();
    }
    m = redbuf[0];
    __syncthreads();

    float sum = 0.f;
    for (int t = threadIdx.x; t < T; t += 256) {
        float e = expf(sc[t] - m);
        sc[t] = e;
        sum += e;
    }
    redbuf[threadIdx.x] = sum;
    __syncthreads();
    for (int s = 128; s > 0; s >>= 1) {
        if (threadIdx.x < s) redbuf[threadIdx.x] += redbuf[threadIdx.x + s];
        __syncthreads();
    }
    const float inv = 1.f / redbuf[0];
    __syncthreads();

    for (int t = threadIdx.x; t < T; t += 256) attn[b*T + t] = sc[t] * inv;
}

// ---------------------------------------------------------------------------
// Kernel 4/5: context = sum_t attn * values
// ---------------------------------------------------------------------------
__global__ void __launch_bounds__(256)
context_partial_kernel(const float* __restrict__ values,
                       const float* __restrict__ attn) {
    const int ts = blockIdx.x;
    const int b  = blockIdx.y;
    const int t0 = ts * (T / TS);
    const int tid = threadIdx.x;

    __shared__ float w[T / TS];
    if (tid < T / TS) w[tid] = attn[b*T + t0 + tid];
    __syncthreads();

    const float4* vp = (const float4*)(values + ((size_t)b*T + t0) * D) + tid;
    float4 acc = make_float4(0.f, 0.f, 0.f, 0.f);
    #pragma unroll 4
    for (int t = 0; t < T / TS; t++) {
        float4 v = vp[(size_t)t * (D/4)];
        float wt = w[t];
        acc.x += wt * v.x; acc.y += wt * v.y;
        acc.z += wt * v.z; acc.w += wt * v.w;
    }
    ((float4*)(g_ctxp + ((size_t)ts*B + b) * D))[tid] = acc;
}

__global__ void context_reduce_kernel(float* __restrict__ ctx) {
    int i = blockIdx.x * 256 + threadIdx.x;
    float s = 0.f;
    #pragma unroll
    for (int p = 0; p < TS; p++) s += g_ctxp[(size_t)p*B*D + i];
    ctx[i] = s;
}

// ---------------------------------------------------------------------------
extern "C" void kernel_launch(void* const* d_in, const int* in_sizes, int n_in,
                              void* d_out, int out_size) {
    const float* values = (const float*)d_in[0];
    const float* query  = (const float*)d_in[1];
    const float* mask   = (const float*)d_in[2];
    const float* W1     = (const float*)d_in[3];
    const float* b1     = (const float*)d_in[4];
    const float* W2     = (const float*)d_in[5];
    const float* b2     = (const float*)d_in[6];
    const float* Vv     = (const float*)d_in[7];
    const float* bV     = (const float*)d_in[8];

    float* ctx  = (float*)d_out;
    float* attn = (float*)d_out + B*D;

    cudaFuncSetAttribute(score_gemm_tc,  cudaFuncAttributeMaxDynamicSharedMemorySize, SMEM_BYTES);
    cudaFuncSetAttribute(score_gemm_mma, cudaFuncAttributeMaxDynamicSharedMemorySize, FB_SMEM);

    prep_kernel<<<8352, 256>>>(values, W1, query, W2, b1, b2);

    // Exactly one of these has a body (compile-time arch feature selection).
    score_gemm_tc <<<NROWS/GM, NTHREADS, SMEM_BYTES>>>(values, Vv);
    score_gemm_mma<<<NROWS/128, 256, FB_SMEM>>>(values, Vv);

    softmax_kernel<<<B, 256>>>(mask, bV, attn);
    dim3 cgrid(TS, B);
    context_partial_kernel<<<cgrid, 256>>>(values, attn);
    context_reduce_kernel<<<(B*D)/256, 256>>>(ctx);
}